// round 3
// baseline (speedup 1.0000x reference)
#include <cuda_runtime.h>
#include <cuda_bf16.h>
#include <math.h>

#define BB 4
#define NQ 2304
#define NT 2312           // NQ + 8 summary tokens
#define CDIM 512
#define HH 8
#define DD 64
#define M1 (BB * NT)      // 9248
#define M3 (BB * NQ)      // 9216
#define QKV_ELEMS (BB * HH * NT * DD)   // 4,734,976

// Scratch (no allocations allowed)
__device__ float g_q[QKV_ELEMS];
__device__ float g_k[QKV_ELEMS];
__device__ float g_v[QKV_ELEMS];
__device__ float g_o[QKV_ELEMS];

// ---------------------------------------------------------------------------
// Kernel 1: QKV GEMM.  A = concat(X_flat, S_tokens) (M1 x 512), B = Wqkv
// (512 x 1536). Epilogue scatters into g_q/g_k/g_v with layout [b][h][t][d].
// ---------------------------------------------------------------------------
__global__ void __launch_bounds__(256) qkv_gemm_kernel(
    const float* __restrict__ X, const float* __restrict__ S,
    const float* __restrict__ W)
{
    __shared__ float As[8][128];
    __shared__ float Bs[8][128];

    const int m0 = blockIdx.y * 128;
    const int n0 = blockIdx.x * 128;
    const int tid = threadIdx.x;
    const int tx = tid & 15;       // 0..15
    const int ty = tid >> 4;       // 0..15

    float acc[8][8];
#pragma unroll
    for (int i = 0; i < 8; i++)
#pragma unroll
        for (int j = 0; j < 8; j++) acc[i][j] = 0.0f;

    // A-load assignment: 128 rows x 8 cols, each thread one float4
    const int arow = tid >> 1;           // 0..127
    const int acol = (tid & 1) * 4;      // 0 or 4
    // B-load assignment: 8 rows x 128 cols
    const int brow = tid >> 5;           // 0..7
    const int bcol = (tid & 31) * 4;     // 0..124

    const float* aptr = nullptr;
    {
        int m = m0 + arow;
        if (m < M1) {
            int b = m / NT;
            int t = m - b * NT;
            if (t < NQ)
                aptr = X + ((size_t)b * NQ + t) * CDIM;
            else
                aptr = S + ((size_t)b * 8 + (t - NQ)) * CDIM;
        }
    }

    for (int k0 = 0; k0 < CDIM; k0 += 8) {
        float4 av = make_float4(0.f, 0.f, 0.f, 0.f);
        if (aptr) av = *(const float4*)(aptr + k0 + acol);
        As[acol + 0][arow] = av.x;
        As[acol + 1][arow] = av.y;
        As[acol + 2][arow] = av.z;
        As[acol + 3][arow] = av.w;

        float4 bv = *(const float4*)(W + (size_t)(k0 + brow) * 1536 + n0 + bcol);
        *(float4*)&Bs[brow][bcol] = bv;
        __syncthreads();

#pragma unroll
        for (int kk = 0; kk < 8; kk++) {
            float a[8], b_[8];
            *(float4*)&a[0] = *(float4*)&As[kk][ty * 4];
            *(float4*)&a[4] = *(float4*)&As[kk][64 + ty * 4];
            *(float4*)&b_[0] = *(float4*)&Bs[kk][tx * 4];
            *(float4*)&b_[4] = *(float4*)&Bs[kk][64 + tx * 4];
#pragma unroll
            for (int i = 0; i < 8; i++)
#pragma unroll
                for (int j = 0; j < 8; j++)
                    acc[i][j] = fmaf(a[i], b_[j], acc[i][j]);
        }
        __syncthreads();
    }

    // Epilogue: scatter to q/k/v in [b][h][t][d] layout
#pragma unroll
    for (int ih = 0; ih < 2; ih++) {
#pragma unroll
        for (int ii = 0; ii < 4; ii++) {
            int m = m0 + ih * 64 + ty * 4 + ii;
            if (m >= M1) continue;
            int b = m / NT;
            int t = m - b * NT;
#pragma unroll
            for (int jh = 0; jh < 2; jh++) {
#pragma unroll
                for (int jj = 0; jj < 4; jj++) {
                    int c = n0 + jh * 64 + tx * 4 + jj;
                    int which = c >> 9;     // 0=q 1=k 2=v
                    int cc = c & 511;
                    int h = cc >> 6;
                    int d = cc & 63;
                    float* dst = (which == 0) ? g_q : (which == 1) ? g_k : g_v;
                    dst[(((size_t)b * HH + h) * NT + t) * DD + d] =
                        acc[ih * 4 + ii][jh * 4 + jj];
                }
            }
        }
    }
}

// ---------------------------------------------------------------------------
// Kernel 2: L2-normalize each 64-elem row of g_q and g_k (warp per row).
// ---------------------------------------------------------------------------
__global__ void l2norm_kernel()
{
    const int R = BB * HH * NT;   // rows per tensor
    int gwarp = (blockIdx.x * blockDim.x + threadIdx.x) >> 5;
    int lane = threadIdx.x & 31;
    if (gwarp >= 2 * R) return;
    float* ptr = ((gwarp < R) ? g_q : g_k) + (size_t)(gwarp % R) * DD;
    float x0 = ptr[lane];
    float x1 = ptr[lane + 32];
    float s = x0 * x0 + x1 * x1;
#pragma unroll
    for (int off = 16; off >= 1; off >>= 1)
        s += __shfl_xor_sync(0xffffffffu, s, off);
    float n = sqrtf(s);
    n = fmaxf(n, 1e-12f);
    float inv = 1.0f / n;
    ptr[lane] = x0 * inv;
    ptr[lane + 32] = x1 * inv;
}

// ---------------------------------------------------------------------------
// Kernel 3: Flash attention (fp32). grid = (ceil(NT/64), B*H), 256 threads.
// Each block: 64 queries, loop over 64-key tiles, online softmax.
// Dynamic smem: Qs[d][i], Ks[d][j], Vs[j][d], Ps[j][i], stride 68.
// ---------------------------------------------------------------------------
#define SSTR 68
#define SM_TILE (64 * SSTR)

__global__ void __launch_bounds__(256) attn_kernel(const float* __restrict__ temp)
{
    extern __shared__ float sm[];
    float* Qs = sm;                // [64][68]  transposed: [d][i]
    float* Ks = sm + SM_TILE;      // [d][j]
    float* Vs = sm + 2 * SM_TILE;  // [j][d]
    float* Ps = sm + 3 * SM_TILE;  // [j][i]

    const int bh = blockIdx.y;
    const int h = bh & (HH - 1);
    const int qt = blockIdx.x;
    const int tid = threadIdx.x;
    const int tx = tid & 15;
    const int ty = tid >> 4;
    const int i0 = ty * 4;
    const int j0 = tx * 4;
    const float T = temp[h];

    const float* qbase = g_q + (size_t)bh * NT * DD;
    const float* kbase = g_k + (size_t)bh * NT * DD;
    const float* vbase = g_v + (size_t)bh * NT * DD;

    // Load Q tile (transposed into Qs[d][i])
#pragma unroll
    for (int rep = 0; rep < 4; rep++) {
        int lin = rep * 256 + tid;     // 0..1023
        int i = lin >> 4;              // 0..63
        int d4 = (lin & 15) * 4;
        int ig = qt * 64 + i;
        float4 v = make_float4(0.f, 0.f, 0.f, 0.f);
        if (ig < NT) v = *(const float4*)(qbase + (size_t)ig * DD + d4);
        Qs[(d4 + 0) * SSTR + i] = v.x;
        Qs[(d4 + 1) * SSTR + i] = v.y;
        Qs[(d4 + 2) * SSTR + i] = v.z;
        Qs[(d4 + 3) * SSTR + i] = v.w;
    }

    float o[4][4];
    float m_run[4], l_run[4];
#pragma unroll
    for (int a = 0; a < 4; a++) {
        m_run[a] = -1e30f;
        l_run[a] = 0.0f;
#pragma unroll
        for (int b = 0; b < 4; b++) o[a][b] = 0.0f;
    }

    const int nkt = (NT + 63) / 64;   // 37
    for (int kt = 0; kt < nkt; kt++) {
        __syncthreads();   // protect smem reuse (and first-time Q visibility)
        // Load K (transposed) and V (natural)
#pragma unroll
        for (int rep = 0; rep < 4; rep++) {
            int lin = rep * 256 + tid;
            int j = lin >> 4;
            int d4 = (lin & 15) * 4;
            int jg = kt * 64 + j;
            float4 kv = make_float4(0.f, 0.f, 0.f, 0.f);
            float4 vv = make_float4(0.f, 0.f, 0.f, 0.f);
            if (jg < NT) {
                kv = *(const float4*)(kbase + (size_t)jg * DD + d4);
                vv = *(const float4*)(vbase + (size_t)jg * DD + d4);
            }
            Ks[(d4 + 0) * SSTR + j] = kv.x;
            Ks[(d4 + 1) * SSTR + j] = kv.y;
            Ks[(d4 + 2) * SSTR + j] = kv.z;
            Ks[(d4 + 3) * SSTR + j] = kv.w;
            *(float4*)&Vs[j * SSTR + d4] = vv;
        }
        __syncthreads();

        // S = Q @ K^T  (4x4 per thread)
        float s[4][4];
#pragma unroll
        for (int a = 0; a < 4; a++)
#pragma unroll
            for (int b = 0; b < 4; b++) s[a][b] = 0.0f;

#pragma unroll 4
        for (int d = 0; d < 64; d++) {
            float4 qa = *(float4*)&Qs[d * SSTR + i0];
            float4 kb = *(float4*)&Ks[d * SSTR + j0];
            float aq[4] = {qa.x, qa.y, qa.z, qa.w};
            float bk[4] = {kb.x, kb.y, kb.z, kb.w};
#pragma unroll
            for (int a = 0; a < 4; a++)
#pragma unroll
                for (int b = 0; b < 4; b++)
                    s[a][b] = fmaf(aq[a], bk[b], s[a][b]);
        }

        // temperature + mask
        int jbase = kt * 64 + j0;
#pragma unroll
        for (int a = 0; a < 4; a++)
#pragma unroll
            for (int b = 0; b < 4; b++)
                s[a][b] = (jbase + b < NT) ? s[a][b] * T : -1e30f;

        // online softmax (row stats shared across 16-lane tx groups via shfl)
#pragma unroll
        for (int a = 0; a < 4; a++) {
            float mloc = fmaxf(fmaxf(s[a][0], s[a][1]), fmaxf(s[a][2], s[a][3]));
#pragma unroll
            for (int off = 8; off >= 1; off >>= 1)
                mloc = fmaxf(mloc, __shfl_xor_sync(0xffffffffu, mloc, off));
            float mnew = fmaxf(m_run[a], mloc);
            float scale = __expf(m_run[a] - mnew);
            float lloc = 0.0f;
#pragma unroll
            for (int b = 0; b < 4; b++) {
                float p = __expf(s[a][b] - mnew);
                s[a][b] = p;
                lloc += p;
            }
#pragma unroll
            for (int off = 8; off >= 1; off >>= 1)
                lloc += __shfl_xor_sync(0xffffffffu, lloc, off);
            l_run[a] = l_run[a] * scale + lloc;
            m_run[a] = mnew;
#pragma unroll
            for (int b = 0; b < 4; b++) o[a][b] *= scale;
            // store P transposed: Ps[j][i]
#pragma unroll
            for (int b = 0; b < 4; b++)
                Ps[(j0 + b) * SSTR + (i0 + a)] = s[a][b];
        }
        __syncthreads();

        // O += P @ V   (output cols d0 = tx*4 == j0)
#pragma unroll 4
        for (int j = 0; j < 64; j++) {
            float4 pa = *(float4*)&Ps[j * SSTR + i0];
            float4 vb = *(float4*)&Vs[j * SSTR + j0];
            float ap[4] = {pa.x, pa.y, pa.z, pa.w};
            float bv[4] = {vb.x, vb.y, vb.z, vb.w};
#pragma unroll
            for (int a = 0; a < 4; a++)
#pragma unroll
                for (int b = 0; b < 4; b++)
                    o[a][b] = fmaf(ap[a], bv[b], o[a][b]);
        }
    }

    // Epilogue: normalize by l, write to g_o[bh][t][d]
#pragma unroll
    for (int a = 0; a < 4; a++) {
        int ig = qt * 64 + i0 + a;
        if (ig >= NT) continue;
        float inv = 1.0f / l_run[a];
        float4 w;
        w.x = o[a][0] * inv;
        w.y = o[a][1] * inv;
        w.z = o[a][2] * inv;
        w.w = o[a][3] * inv;
        *(float4*)&g_o[((size_t)bh * NT + ig) * DD + j0] = w;
    }
}

// ---------------------------------------------------------------------------
// Kernel 4: output projection. A[m][k] = g_o (remapped), B = Wout (512x512).
// Only rows t < NQ are computed/written. M3 = 9216 = 72*128 exact.
// ---------------------------------------------------------------------------
__global__ void __launch_bounds__(256) out_gemm_kernel(
    const float* __restrict__ Wout, float* __restrict__ out)
{
    __shared__ float As[8][128];
    __shared__ float Bs[8][128];

    const int m0 = blockIdx.y * 128;
    const int n0 = blockIdx.x * 128;
    const int tid = threadIdx.x;
    const int tx = tid & 15;
    const int ty = tid >> 4;

    float acc[8][8];
#pragma unroll
    for (int i = 0; i < 8; i++)
#pragma unroll
        for (int j = 0; j < 8; j++) acc[i][j] = 0.0f;

    const int arow = tid >> 1;
    const int acol = (tid & 1) * 4;
    const int brow = tid >> 5;
    const int bcol = (tid & 31) * 4;

    const int m = m0 + arow;
    const int b = m / NQ;
    const int t = m - b * NQ;

    for (int k0 = 0; k0 < CDIM; k0 += 8) {
        int k = k0 + acol;
        int h = k >> 6;
        int d = k & 63;
        float4 av = *(const float4*)(g_o + (((size_t)b * HH + h) * NT + t) * DD + d);
        As[acol + 0][arow] = av.x;
        As[acol + 1][arow] = av.y;
        As[acol + 2][arow] = av.z;
        As[acol + 3][arow] = av.w;

        float4 bv = *(const float4*)(Wout + (size_t)(k0 + brow) * CDIM + n0 + bcol);
        *(float4*)&Bs[brow][bcol] = bv;
        __syncthreads();

#pragma unroll
        for (int kk = 0; kk < 8; kk++) {
            float a[8], b_[8];
            *(float4*)&a[0] = *(float4*)&As[kk][ty * 4];
            *(float4*)&a[4] = *(float4*)&As[kk][64 + ty * 4];
            *(float4*)&b_[0] = *(float4*)&Bs[kk][tx * 4];
            *(float4*)&b_[4] = *(float4*)&Bs[kk][64 + tx * 4];
#pragma unroll
            for (int i = 0; i < 8; i++)
#pragma unroll
                for (int j = 0; j < 8; j++)
                    acc[i][j] = fmaf(a[i], b_[j], acc[i][j]);
        }
        __syncthreads();
    }

#pragma unroll
    for (int ih = 0; ih < 2; ih++) {
#pragma unroll
        for (int ii = 0; ii < 4; ii++) {
            int mm = m0 + ih * 64 + ty * 4 + ii;
            int bb = mm / NQ;
            int tt = mm - bb * NQ;
            float* orow = out + ((size_t)bb * NQ + tt) * CDIM + n0;
#pragma unroll
            for (int jh = 0; jh < 2; jh++) {
                float4 w;
                w.x = acc[ih * 4 + ii][jh * 4 + 0];
                w.y = acc[ih * 4 + ii][jh * 4 + 1];
                w.z = acc[ih * 4 + ii][jh * 4 + 2];
                w.w = acc[ih * 4 + ii][jh * 4 + 3];
                *(float4*)(orow + jh * 64 + tx * 4) = w;
            }
        }
    }
}

// ---------------------------------------------------------------------------
extern "C" void kernel_launch(void* const* d_in, const int* in_sizes, int n_in,
                              void* d_out, int out_size)
{
    const float* X    = (const float*)d_in[0];   // (4,2304,512)
    const float* S    = (const float*)d_in[1];   // (4,8,512)
    const float* Wqkv = (const float*)d_in[2];   // (512,1536)
    const float* Wout = (const float*)d_in[3];   // (512,512)
    const float* temp = (const float*)d_in[4];   // (8,1,1)
    float* out = (float*)d_out;                  // (4,2304,512)

    // 1. QKV GEMM
    {
        dim3 grid(1536 / 128, (M1 + 127) / 128);   // (12, 73)
        qkv_gemm_kernel<<<grid, 256>>>(X, S, Wqkv);
    }
    // 2. L2 normalize q and k
    {
        int rows = 2 * BB * HH * NT;               // 147968 row-warps
        int blocks = (rows + 7) / 8;
        l2norm_kernel<<<blocks, 256>>>();
    }
    // 3. Attention
    {
        size_t smem = 4 * SM_TILE * sizeof(float); // 69632 bytes
        // Idempotent, capture-legal (not a stream op). Tolerate redundant calls.
        (void)cudaFuncSetAttribute(attn_kernel,
                                   cudaFuncAttributeMaxDynamicSharedMemorySize,
                                   (int)smem);
        dim3 grid((NT + 63) / 64, BB * HH);        // (37, 32)
        attn_kernel<<<grid, 256, smem>>>(temp);
    }
    // 4. Output projection
    {
        dim3 grid(CDIM / 128, M3 / 128);           // (4, 72)
        out_gemm_kernel<<<grid, 256>>>(Wout, out);
    }
}

// round 5
// speedup vs baseline: 2.7506x; 2.7506x over previous
#include <cuda_runtime.h>
#include <cuda_fp16.h>
#include <cuda_bf16.h>
#include <math.h>
#include <stdint.h>

#define BB 4
#define NQ 2304
#define NT 2312           // NQ + 8 summary tokens
#define CDIM 512
#define HH 8
#define DD 64
#define M1 (BB * NT)      // 9248
#define M3 (BB * NQ)      // 9216
#define QKV_ELEMS (BB * HH * NT * DD)   // 4,734,976
#define NKT 37            // ceil(NT/64) key tiles
#define LASTKT 36
#define NQT 19            // ceil(NT/128) query tiles

// Scratch (no allocations allowed)
__device__ float  g_q[QKV_ELEMS];
__device__ float  g_k[QKV_ELEMS];
__device__ __half g_qh[QKV_ELEMS];
__device__ __half g_kh[QKV_ELEMS];
__device__ __half g_vh[QKV_ELEMS];
__device__ float  g_o[QKV_ELEMS];

// ---------------------------------------------------------------------------
// MMA helpers
// ---------------------------------------------------------------------------
static __device__ __forceinline__ uint32_t smem_u32(const void* p) {
    return (uint32_t)__cvta_generic_to_shared(p);
}

#define LDSM4(r0, r1, r2, r3, addr)                                            \
    asm volatile("ldmatrix.sync.aligned.m8n8.x4.shared.b16 {%0,%1,%2,%3}, [%4];" \
                 : "=r"(r0), "=r"(r1), "=r"(r2), "=r"(r3) : "r"(addr))

#define LDSM4T(r0, r1, r2, r3, addr)                                           \
    asm volatile("ldmatrix.sync.aligned.m8n8.x4.trans.shared.b16 {%0,%1,%2,%3}, [%4];" \
                 : "=r"(r0), "=r"(r1), "=r"(r2), "=r"(r3) : "r"(addr))

static __device__ __forceinline__ void mma_16816(
    float c[4], uint32_t a0, uint32_t a1, uint32_t a2, uint32_t a3,
    uint32_t b0, uint32_t b1)
{
    asm volatile(
        "mma.sync.aligned.m16n8k16.row.col.f32.f16.f16.f32 "
        "{%0,%1,%2,%3},{%4,%5,%6,%7},{%8,%9},{%0,%1,%2,%3};"
        : "+f"(c[0]), "+f"(c[1]), "+f"(c[2]), "+f"(c[3])
        : "r"(a0), "r"(a1), "r"(a2), "r"(a3), "r"(b0), "r"(b1));
}

static __device__ __forceinline__ uint32_t pack_half2(float x, float y) {
    __half2 h = __floats2half2_rn(x, y);
    return reinterpret_cast<uint32_t&>(h);
}

// ---------------------------------------------------------------------------
// Kernel 1: QKV GEMM (fp32 FFMA).  Epilogue scatters q,k (fp32, pre-norm) and
// v (fp16) into [b][h][t][d] layout.
// ---------------------------------------------------------------------------
__global__ void __launch_bounds__(256) qkv_gemm_kernel(
    const float* __restrict__ X, const float* __restrict__ S,
    const float* __restrict__ W)
{
    __shared__ float As[8][128];
    __shared__ float Bs[8][128];

    const int m0 = blockIdx.y * 128;
    const int n0 = blockIdx.x * 128;
    const int tid = threadIdx.x;
    const int tx = tid & 15;
    const int ty = tid >> 4;

    float acc[8][8];
#pragma unroll
    for (int i = 0; i < 8; i++)
#pragma unroll
        for (int j = 0; j < 8; j++) acc[i][j] = 0.0f;

    const int arow = tid >> 1;
    const int acol = (tid & 1) * 4;
    const int brow = tid >> 5;
    const int bcol = (tid & 31) * 4;

    const float* aptr = nullptr;
    {
        int m = m0 + arow;
        if (m < M1) {
            int b = m / NT;
            int t = m - b * NT;
            if (t < NQ)
                aptr = X + ((size_t)b * NQ + t) * CDIM;
            else
                aptr = S + ((size_t)b * 8 + (t - NQ)) * CDIM;
        }
    }

    for (int k0 = 0; k0 < CDIM; k0 += 8) {
        float4 av = make_float4(0.f, 0.f, 0.f, 0.f);
        if (aptr) av = *(const float4*)(aptr + k0 + acol);
        As[acol + 0][arow] = av.x;
        As[acol + 1][arow] = av.y;
        As[acol + 2][arow] = av.z;
        As[acol + 3][arow] = av.w;

        float4 bv = *(const float4*)(W + (size_t)(k0 + brow) * 1536 + n0 + bcol);
        *(float4*)&Bs[brow][bcol] = bv;
        __syncthreads();

#pragma unroll
        for (int kk = 0; kk < 8; kk++) {
            float a[8], b_[8];
            *(float4*)&a[0] = *(float4*)&As[kk][ty * 4];
            *(float4*)&a[4] = *(float4*)&As[kk][64 + ty * 4];
            *(float4*)&b_[0] = *(float4*)&Bs[kk][tx * 4];
            *(float4*)&b_[4] = *(float4*)&Bs[kk][64 + tx * 4];
#pragma unroll
            for (int i = 0; i < 8; i++)
#pragma unroll
                for (int j = 0; j < 8; j++)
                    acc[i][j] = fmaf(a[i], b_[j], acc[i][j]);
        }
        __syncthreads();
    }

#pragma unroll
    for (int ih = 0; ih < 2; ih++) {
#pragma unroll
        for (int ii = 0; ii < 4; ii++) {
            int m = m0 + ih * 64 + ty * 4 + ii;
            if (m >= M1) continue;
            int b = m / NT;
            int t = m - b * NT;
#pragma unroll
            for (int jh = 0; jh < 2; jh++) {
#pragma unroll
                for (int jj = 0; jj < 4; jj++) {
                    int c = n0 + jh * 64 + tx * 4 + jj;
                    int which = c >> 9;     // 0=q 1=k 2=v
                    int cc = c & 511;
                    int h = cc >> 6;
                    int d = cc & 63;
                    size_t idx = (((size_t)b * HH + h) * NT + t) * DD + d;
                    float val = acc[ih * 4 + ii][jh * 4 + jj];
                    if (which == 0)      g_q[idx] = val;
                    else if (which == 1) g_k[idx] = val;
                    else                 g_vh[idx] = __float2half_rn(val);
                }
            }
        }
    }
}

// ---------------------------------------------------------------------------
// Kernel 2: L2-normalize rows of q,k; output fp16 to g_qh/g_kh.
// ---------------------------------------------------------------------------
__global__ void l2norm_kernel()
{
    const int R = BB * HH * NT;
    int gwarp = (blockIdx.x * blockDim.x + threadIdx.x) >> 5;
    int lane = threadIdx.x & 31;
    if (gwarp >= 2 * R) return;
    bool isq = gwarp < R;
    size_t row = (size_t)(gwarp % R) * DD;
    const float* src = (isq ? g_q : g_k) + row;
    __half* dst = (isq ? g_qh : g_kh) + row;
    float x0 = src[lane];
    float x1 = src[lane + 32];
    float s = x0 * x0 + x1 * x1;
#pragma unroll
    for (int off = 16; off >= 1; off >>= 1)
        s += __shfl_xor_sync(0xffffffffu, s, off);
    float n = fmaxf(sqrtf(s), 1e-12f);
    float inv = 1.0f / n;
    dst[lane]      = __float2half_rn(x0 * inv);
    dst[lane + 32] = __float2half_rn(x1 * inv);
}

// ---------------------------------------------------------------------------
// Kernel 3: Flash attention with fp16 tensor-core MMA, fp32 accumulate.
// Block = 256 threads (8 warps), 128 queries; key tiles of 64.
// ---------------------------------------------------------------------------
__global__ void __launch_bounds__(256) attn_mma_kernel(const float* __restrict__ temp)
{
    __shared__ __half Qs[128 * 72];
    __shared__ __half Ks[64 * 72];
    __shared__ __half Vs[64 * 72];

    const int bh = blockIdx.y;
    const int h = bh & (HH - 1);
    const int qt = blockIdx.x;
    const int tid = threadIdx.x;
    const int w = tid >> 5;
    const int lane = tid & 31;
    const int grp = lane >> 2;      // row within 8
    const int qd = lane & 3;        // quad
    const float T = temp[h];

    const __half* qbase = g_qh + (size_t)bh * NT * DD;
    const __half* kbase = g_kh + (size_t)bh * NT * DD;
    const __half* vbase = g_vh + (size_t)bh * NT * DD;

    // ---- stage Q tile (128 x 64 fp16), zero-padded ----
#pragma unroll
    for (int it = 0; it < 4; it++) {
        int idx = it * 256 + tid;           // 0..1023
        int r = idx >> 3;
        int c8 = (idx & 7) * 8;
        int ig = qt * 128 + r;
        int4 val = make_int4(0, 0, 0, 0);
        if (ig < NT) val = *(const int4*)(qbase + (size_t)ig * DD + c8);
        *(int4*)(Qs + r * 72 + c8) = val;
    }
    __syncthreads();

    // ldmatrix per-lane row/col selectors
    const int rowA = (lane & 7) + (((lane >> 3) & 1) << 3);   // Q (A) and V (trans B)
    const int colA = (lane >> 4) << 3;
    const int rowB = (lane & 7) + ((lane >> 4) << 3);         // K (B)
    const int colB = ((lane >> 3) & 1) << 3;

    // ---- Q A-fragments (4 k-steps of 16) ----
    uint32_t aq[4][4];
    {
        const int m0 = w * 16;
#pragma unroll
        for (int ks = 0; ks < 4; ks++) {
            uint32_t addr = smem_u32(Qs + (m0 + rowA) * 72 + ks * 16 + colA);
            LDSM4(aq[ks][0], aq[ks][1], aq[ks][2], aq[ks][3], addr);
        }
    }

    float o[8][4];
#pragma unroll
    for (int c = 0; c < 8; c++)
#pragma unroll
        for (int j = 0; j < 4; j++) o[c][j] = 0.0f;
    float m0r = -1e30f, m1r = -1e30f, l0 = 0.0f, l1 = 0.0f;

    for (int kt = 0; kt < NKT; kt++) {
        __syncthreads();
        // ---- load K,V tiles (64 x 64 fp16 each) ----
#pragma unroll
        for (int it = 0; it < 2; it++) {
            int idx = it * 256 + tid;       // 0..511
            int r = idx >> 3;
            int c8 = (idx & 7) * 8;
            int jg = kt * 64 + r;
            int4 kv = make_int4(0, 0, 0, 0);
            int4 vv = make_int4(0, 0, 0, 0);
            if (jg < NT) {
                kv = *(const int4*)(kbase + (size_t)jg * DD + c8);
                vv = *(const int4*)(vbase + (size_t)jg * DD + c8);
            }
            *(int4*)(Ks + r * 72 + c8) = kv;
            *(int4*)(Vs + r * 72 + c8) = vv;
        }
        __syncthreads();

        // ---- S = Q @ K^T ----
        float s[8][4];
#pragma unroll
        for (int c = 0; c < 8; c++)
#pragma unroll
            for (int j = 0; j < 4; j++) s[c][j] = 0.0f;

#pragma unroll
        for (int ks = 0; ks < 4; ks++) {
#pragma unroll
            for (int np = 0; np < 4; np++) {
                uint32_t b0, b1, b2, b3;
                uint32_t addr = smem_u32(Ks + (np * 16 + rowB) * 72 + ks * 16 + colB);
                LDSM4(b0, b1, b2, b3, addr);
                mma_16816(s[np * 2],     aq[ks][0], aq[ks][1], aq[ks][2], aq[ks][3], b0, b1);
                mma_16816(s[np * 2 + 1], aq[ks][0], aq[ks][1], aq[ks][2], aq[ks][3], b2, b3);
            }
        }

        // ---- temperature + tail mask (last tile: only chunk 0 = 8 keys valid) ----
        const bool lastk = (kt == LASTKT);
#pragma unroll
        for (int c = 0; c < 8; c++) {
#pragma unroll
            for (int j = 0; j < 4; j++) {
                float v = s[c][j] * T;
                if (lastk && c > 0) v = -1e30f;
                s[c][j] = v;
            }
        }

        // ---- online softmax (two rows per thread: grp, grp+8) ----
        float mx0 = -1e30f, mx1 = -1e30f;
#pragma unroll
        for (int c = 0; c < 8; c++) {
            mx0 = fmaxf(mx0, fmaxf(s[c][0], s[c][1]));
            mx1 = fmaxf(mx1, fmaxf(s[c][2], s[c][3]));
        }
        mx0 = fmaxf(mx0, __shfl_xor_sync(0xffffffffu, mx0, 1));
        mx0 = fmaxf(mx0, __shfl_xor_sync(0xffffffffu, mx0, 2));
        mx1 = fmaxf(mx1, __shfl_xor_sync(0xffffffffu, mx1, 1));
        mx1 = fmaxf(mx1, __shfl_xor_sync(0xffffffffu, mx1, 2));

        float mn0 = fmaxf(m0r, mx0);
        float mn1 = fmaxf(m1r, mx1);
        float sc0 = __expf(m0r - mn0);
        float sc1 = __expf(m1r - mn1);

        float sum0 = 0.0f, sum1 = 0.0f;
        uint32_t ph0[8], ph1[8];
#pragma unroll
        for (int c = 0; c < 8; c++) {
            float p00 = __expf(s[c][0] - mn0);
            float p01 = __expf(s[c][1] - mn0);
            float p10 = __expf(s[c][2] - mn1);
            float p11 = __expf(s[c][3] - mn1);
            sum0 += p00 + p01;
            sum1 += p10 + p11;
            ph0[c] = pack_half2(p00, p01);
            ph1[c] = pack_half2(p10, p11);
        }
        sum0 += __shfl_xor_sync(0xffffffffu, sum0, 1);
        sum0 += __shfl_xor_sync(0xffffffffu, sum0, 2);
        sum1 += __shfl_xor_sync(0xffffffffu, sum1, 1);
        sum1 += __shfl_xor_sync(0xffffffffu, sum1, 2);

        l0 = l0 * sc0 + sum0;
        l1 = l1 * sc1 + sum1;
        m0r = mn0;
        m1r = mn1;
#pragma unroll
        for (int c = 0; c < 8; c++) {
            o[c][0] *= sc0; o[c][1] *= sc0;
            o[c][2] *= sc1; o[c][3] *= sc1;
        }

        // ---- O += P @ V ----
#pragma unroll
        for (int ks = 0; ks < 4; ks++) {
            uint32_t a0 = ph0[2 * ks], a1 = ph1[2 * ks];
            uint32_t a2 = ph0[2 * ks + 1], a3 = ph1[2 * ks + 1];
#pragma unroll
            for (int np = 0; np < 4; np++) {
                uint32_t b0, b1, b2, b3;
                uint32_t addr = smem_u32(Vs + (ks * 16 + rowA) * 72 + np * 16 + colA);
                LDSM4T(b0, b1, b2, b3, addr);
                mma_16816(o[np * 2],     a0, a1, a2, a3, b0, b1);
                mma_16816(o[np * 2 + 1], a0, a1, a2, a3, b2, b3);
            }
        }
    }

    // ---- epilogue: normalize, write g_o ----
    float inv0 = 1.0f / l0;
    float inv1 = 1.0f / l1;
    int t0 = qt * 128 + w * 16 + grp;
    if (t0 < NT) {
        float* dst = g_o + ((size_t)bh * NT + t0) * DD;
#pragma unroll
        for (int c = 0; c < 8; c++) {
            float2 v = make_float2(o[c][0] * inv0, o[c][1] * inv0);
            *(float2*)(dst + c * 8 + qd * 2) = v;
        }
    }
    int t1 = t0 + 8;
    if (t1 < NT) {
        float* dst = g_o + ((size_t)bh * NT + t1) * DD;
#pragma unroll
        for (int c = 0; c < 8; c++) {
            float2 v = make_float2(o[c][2] * inv1, o[c][3] * inv1);
            *(float2*)(dst + c * 8 + qd * 2) = v;
        }
    }
}

// ---------------------------------------------------------------------------
// Kernel 4: output projection (fp32 FFMA), reads g_o remapped.
// ---------------------------------------------------------------------------
__global__ void __launch_bounds__(256) out_gemm_kernel(
    const float* __restrict__ Wout, float* __restrict__ out)
{
    __shared__ float As[8][128];
    __shared__ float Bs[8][128];

    const int m0 = blockIdx.y * 128;
    const int n0 = blockIdx.x * 128;
    const int tid = threadIdx.x;
    const int tx = tid & 15;
    const int ty = tid >> 4;

    float acc[8][8];
#pragma unroll
    for (int i = 0; i < 8; i++)
#pragma unroll
        for (int j = 0; j < 8; j++) acc[i][j] = 0.0f;

    const int arow = tid >> 1;
    const int acol = (tid & 1) * 4;
    const int brow = tid >> 5;
    const int bcol = (tid & 31) * 4;

    const int m = m0 + arow;
    const int b = m / NQ;
    const int t = m - b * NQ;

    for (int k0 = 0; k0 < CDIM; k0 += 8) {
        int k = k0 + acol;
        int h = k >> 6;
        int d = k & 63;
        float4 av = *(const float4*)(g_o + (((size_t)b * HH + h) * NT + t) * DD + d);
        As[acol + 0][arow] = av.x;
        As[acol + 1][arow] = av.y;
        As[acol + 2][arow] = av.z;
        As[acol + 3][arow] = av.w;

        float4 bv = *(const float4*)(Wout + (size_t)(k0 + brow) * CDIM + n0 + bcol);
        *(float4*)&Bs[brow][bcol] = bv;
        __syncthreads();

#pragma unroll
        for (int kk = 0; kk < 8; kk++) {
            float a[8], b_[8];
            *(float4*)&a[0] = *(float4*)&As[kk][ty * 4];
            *(float4*)&a[4] = *(float4*)&As[kk][64 + ty * 4];
            *(float4*)&b_[0] = *(float4*)&Bs[kk][tx * 4];
            *(float4*)&b_[4] = *(float4*)&Bs[kk][64 + tx * 4];
#pragma unroll
            for (int i = 0; i < 8; i++)
#pragma unroll
                for (int j = 0; j < 8; j++)
                    acc[i][j] = fmaf(a[i], b_[j], acc[i][j]);
        }
        __syncthreads();
    }

#pragma unroll
    for (int ih = 0; ih < 2; ih++) {
#pragma unroll
        for (int ii = 0; ii < 4; ii++) {
            int mm = m0 + ih * 64 + ty * 4 + ii;
            int bb = mm / NQ;
            int tt = mm - bb * NQ;
            float* orow = out + ((size_t)bb * NQ + tt) * CDIM + n0;
#pragma unroll
            for (int jh = 0; jh < 2; jh++) {
                float4 wv;
                wv.x = acc[ih * 4 + ii][jh * 4 + 0];
                wv.y = acc[ih * 4 + ii][jh * 4 + 1];
                wv.z = acc[ih * 4 + ii][jh * 4 + 2];
                wv.w = acc[ih * 4 + ii][jh * 4 + 3];
                *(float4*)(orow + jh * 64 + tx * 4) = wv;
            }
        }
    }
}

// ---------------------------------------------------------------------------
extern "C" void kernel_launch(void* const* d_in, const int* in_sizes, int n_in,
                              void* d_out, int out_size)
{
    const float* X    = (const float*)d_in[0];   // (4,2304,512)
    const float* S    = (const float*)d_in[1];   // (4,8,512)
    const float* Wqkv = (const float*)d_in[2];   // (512,1536)
    const float* Wout = (const float*)d_in[3];   // (512,512)
    const float* temp = (const float*)d_in[4];   // (8,1,1)
    float* out = (float*)d_out;                  // (4,2304,512)

    // 1. QKV GEMM
    {
        dim3 grid(1536 / 128, (M1 + 127) / 128);   // (12, 73)
        qkv_gemm_kernel<<<grid, 256>>>(X, S, Wqkv);
    }
    // 2. L2 normalize q,k -> fp16
    {
        int rows = 2 * BB * HH * NT;
        int blocks = (rows + 7) / 8;
        l2norm_kernel<<<blocks, 256>>>();
    }
    // 3. Attention (tensor-core fp16 MMA)
    {
        dim3 grid(NQT, BB * HH);                   // (19, 32)
        attn_mma_kernel<<<grid, 256>>>(temp);
    }
    // 4. Output projection
    {
        dim3 grid(CDIM / 128, M3 / 128);           // (4, 72)
        out_gemm_kernel<<<grid, 256>>>(Wout, out);
    }
}

// round 6
// speedup vs baseline: 4.9863x; 1.8128x over previous
#include <cuda_runtime.h>
#include <cuda_fp16.h>
#include <cuda_bf16.h>
#include <math.h>
#include <stdint.h>

#define BB 4
#define NQ 2304
#define NT 2312           // NQ + 8 summary tokens
#define CDIM 512
#define HH 8
#define DD 64
#define M1 (BB * NT)      // 9248
#define M3 (BB * NQ)      // 9216
#define QKV_ELEMS (BB * HH * NT * DD)   // 4,734,976
#define NKT 37            // ceil(NT/64) key tiles
#define LASTKT 36
#define NQT 19            // ceil(NT/128) query tiles

// Scratch (no allocations allowed)
__device__ float  g_q[QKV_ELEMS];      // pre-norm q (fp32)
__device__ float  g_k[QKV_ELEMS];      // pre-norm k (fp32)
__device__ __half g_qh[QKV_ELEMS];
__device__ __half g_kh[QKV_ELEMS];
__device__ __half g_vh[QKV_ELEMS];
__device__ __half g_oh[QKV_ELEMS];     // attention output (fp16)

// ---------------------------------------------------------------------------
// MMA helpers
// ---------------------------------------------------------------------------
static __device__ __forceinline__ uint32_t smem_u32(const void* p) {
    return (uint32_t)__cvta_generic_to_shared(p);
}

#define LDSM4(r0, r1, r2, r3, addr)                                            \
    asm volatile("ldmatrix.sync.aligned.m8n8.x4.shared.b16 {%0,%1,%2,%3}, [%4];" \
                 : "=r"(r0), "=r"(r1), "=r"(r2), "=r"(r3) : "r"(addr))

#define LDSM4T(r0, r1, r2, r3, addr)                                           \
    asm volatile("ldmatrix.sync.aligned.m8n8.x4.trans.shared.b16 {%0,%1,%2,%3}, [%4];" \
                 : "=r"(r0), "=r"(r1), "=r"(r2), "=r"(r3) : "r"(addr))

static __device__ __forceinline__ void mma_16816(
    float c[4], uint32_t a0, uint32_t a1, uint32_t a2, uint32_t a3,
    uint32_t b0, uint32_t b1)
{
    asm volatile(
        "mma.sync.aligned.m16n8k16.row.col.f32.f16.f16.f32 "
        "{%0,%1,%2,%3},{%4,%5,%6,%7},{%8,%9},{%0,%1,%2,%3};"
        : "+f"(c[0]), "+f"(c[1]), "+f"(c[2]), "+f"(c[3])
        : "r"(a0), "r"(a1), "r"(a2), "r"(a3), "r"(b0), "r"(b1));
}

static __device__ __forceinline__ uint32_t pack_half2(float x, float y) {
    __half2 h = __floats2half2_rn(x, y);
    return reinterpret_cast<uint32_t&>(h);
}

// ---------------------------------------------------------------------------
// Kernel 1: QKV GEMM, fp16 tensor-core MMA, fp32 accumulate.
// A = concat(X,S) (M1 x 512) fp32 -> fp16 in smem; B = Wqkv (512 x 1536).
// Tile 128x128, BK=32, double-buffered smem. 8 warps = 4m x 2n, warp 32x64.
// Epilogue scatters q,k (fp32, pre-norm) and v (fp16) into [b][h][t][d].
// ---------------------------------------------------------------------------
__global__ void __launch_bounds__(256) qkv_mma_kernel(
    const float* __restrict__ X, const float* __restrict__ S,
    const float* __restrict__ W)
{
    __shared__ __half Ah[2][128][40];   // 32 k + 8 pad
    __shared__ __half Bh[2][32][136];   // 128 n + 8 pad

    const int m0 = blockIdx.y * 128;
    const int n0 = blockIdx.x * 128;
    const int tid = threadIdx.x;
    const int w = tid >> 5;
    const int lane = tid & 31;
    const int grp = lane >> 2;
    const int qd = lane & 3;
    const int wm = w >> 1;          // 0..3
    const int wn = w & 1;           // 0..1

    const int rowA = (lane & 7) + (((lane >> 3) & 1) << 3);
    const int colA = (lane >> 4) << 3;

    // A gmem mapping (row fixed per thread)
    const int ar = tid >> 1;
    const int acs = (tid & 1) * 16;
    const float* aptr = nullptr;
    {
        int m = m0 + ar;
        if (m < M1) {
            int b = m / NT;
            int t = m - b * NT;
            aptr = (t < NQ) ? X + ((size_t)b * NQ + t) * CDIM
                            : S + ((size_t)b * 8 + (t - NQ)) * CDIM;
        }
    }
    // B gmem mapping
    const int kr = tid >> 3;
    const int bc = (tid & 7) * 16;

    float4 aPf[4], bPf[4];

#define QKV_LOADR(kt)                                                          \
    do {                                                                       \
        int k0 = (kt) * 32;                                                    \
        if (aptr) {                                                            \
            const float4* ap4 = (const float4*)(aptr + k0 + acs);              \
            aPf[0] = ap4[0]; aPf[1] = ap4[1]; aPf[2] = ap4[2]; aPf[3] = ap4[3];\
        } else {                                                               \
            aPf[0] = aPf[1] = aPf[2] = aPf[3] = make_float4(0.f,0.f,0.f,0.f);  \
        }                                                                      \
        const float4* bp4 = (const float4*)(W + (size_t)(k0 + kr) * 1536 + n0 + bc); \
        bPf[0] = bp4[0]; bPf[1] = bp4[1]; bPf[2] = bp4[2]; bPf[3] = bp4[3];    \
    } while (0)

#define QKV_STORE(buf)                                                         \
    do {                                                                       \
        __half2 ha[8];                                                         \
        ha[0] = __floats2half2_rn(aPf[0].x, aPf[0].y);                         \
        ha[1] = __floats2half2_rn(aPf[0].z, aPf[0].w);                         \
        ha[2] = __floats2half2_rn(aPf[1].x, aPf[1].y);                         \
        ha[3] = __floats2half2_rn(aPf[1].z, aPf[1].w);                         \
        ha[4] = __floats2half2_rn(aPf[2].x, aPf[2].y);                         \
        ha[5] = __floats2half2_rn(aPf[2].z, aPf[2].w);                         \
        ha[6] = __floats2half2_rn(aPf[3].x, aPf[3].y);                         \
        ha[7] = __floats2half2_rn(aPf[3].z, aPf[3].w);                         \
        *(int4*)&Ah[buf][ar][acs]     = *(int4*)&ha[0];                        \
        *(int4*)&Ah[buf][ar][acs + 8] = *(int4*)&ha[4];                        \
        __half2 hb[8];                                                         \
        hb[0] = __floats2half2_rn(bPf[0].x, bPf[0].y);                         \
        hb[1] = __floats2half2_rn(bPf[0].z, bPf[0].w);                         \
        hb[2] = __floats2half2_rn(bPf[1].x, bPf[1].y);                         \
        hb[3] = __floats2half2_rn(bPf[1].z, bPf[1].w);                         \
        hb[4] = __floats2half2_rn(bPf[2].x, bPf[2].y);                         \
        hb[5] = __floats2half2_rn(bPf[2].z, bPf[2].w);                         \
        hb[6] = __floats2half2_rn(bPf[3].x, bPf[3].y);                         \
        hb[7] = __floats2half2_rn(bPf[3].z, bPf[3].w);                         \
        *(int4*)&Bh[buf][kr][bc]     = *(int4*)&hb[0];                         \
        *(int4*)&Bh[buf][kr][bc + 8] = *(int4*)&hb[4];                         \
    } while (0)

    float acc[2][8][4];
#pragma unroll
    for (int i = 0; i < 2; i++)
#pragma unroll
        for (int j = 0; j < 8; j++)
#pragma unroll
            for (int r = 0; r < 4; r++) acc[i][j][r] = 0.0f;

    QKV_LOADR(0);
    QKV_STORE(0);
    __syncthreads();

    for (int kt = 0; kt < 16; kt++) {
        if (kt < 15) QKV_LOADR(kt + 1);
        const int cur = kt & 1;
#pragma unroll
        for (int ks = 0; ks < 2; ks++) {
            uint32_t a[2][4];
#pragma unroll
            for (int mi = 0; mi < 2; mi++) {
                uint32_t addr = smem_u32(&Ah[cur][wm * 32 + mi * 16 + rowA][ks * 16 + colA]);
                LDSM4(a[mi][0], a[mi][1], a[mi][2], a[mi][3], addr);
            }
#pragma unroll
            for (int nc = 0; nc < 4; nc++) {
                uint32_t b0, b1, b2, b3;
                uint32_t addr = smem_u32(&Bh[cur][ks * 16 + rowA][wn * 64 + nc * 16 + colA]);
                LDSM4T(b0, b1, b2, b3, addr);
#pragma unroll
                for (int mi = 0; mi < 2; mi++) {
                    mma_16816(acc[mi][2 * nc],     a[mi][0], a[mi][1], a[mi][2], a[mi][3], b0, b1);
                    mma_16816(acc[mi][2 * nc + 1], a[mi][0], a[mi][1], a[mi][2], a[mi][3], b2, b3);
                }
            }
        }
        if (kt < 15) QKV_STORE(1 - cur);
        __syncthreads();
    }

    // Epilogue: scatter q (fp32), k (fp32), v (fp16)
#pragma unroll
    for (int mi = 0; mi < 2; mi++) {
        int rbase = m0 + wm * 32 + mi * 16 + grp;
#pragma unroll
        for (int nc = 0; nc < 8; nc++) {
            int c = n0 + wn * 64 + nc * 8 + qd * 2;
            int which = c >> 9;
            int h = (c >> 6) & 7;
            int d = c & 63;
#pragma unroll
            for (int rr = 0; rr < 2; rr++) {
                int m = rbase + rr * 8;
                if (m >= M1) continue;
                int b = m / NT;
                int t = m - b * NT;
                size_t idx = (((size_t)b * HH + h) * NT + t) * DD + d;
                float v0 = acc[mi][nc][rr * 2];
                float v1 = acc[mi][nc][rr * 2 + 1];
                if (which == 0)      *(float2*)&g_q[idx] = make_float2(v0, v1);
                else if (which == 1) *(float2*)&g_k[idx] = make_float2(v0, v1);
                else                 *(__half2*)&g_vh[idx] = __floats2half2_rn(v0, v1);
            }
        }
    }
#undef QKV_LOADR
#undef QKV_STORE
}

// ---------------------------------------------------------------------------
// Kernel 2: L2-normalize rows of q,k; output fp16 to g_qh/g_kh.
// ---------------------------------------------------------------------------
__global__ void l2norm_kernel()
{
    const int R = BB * HH * NT;
    int gwarp = (blockIdx.x * blockDim.x + threadIdx.x) >> 5;
    int lane = threadIdx.x & 31;
    if (gwarp >= 2 * R) return;
    bool isq = gwarp < R;
    size_t row = (size_t)(gwarp % R) * DD;
    const float* src = (isq ? g_q : g_k) + row;
    __half* dst = (isq ? g_qh : g_kh) + row;
    float x0 = src[lane];
    float x1 = src[lane + 32];
    float s = x0 * x0 + x1 * x1;
#pragma unroll
    for (int off = 16; off >= 1; off >>= 1)
        s += __shfl_xor_sync(0xffffffffu, s, off);
    float n = fmaxf(sqrtf(s), 1e-12f);
    float inv = 1.0f / n;
    dst[lane]      = __float2half_rn(x0 * inv);
    dst[lane + 32] = __float2half_rn(x1 * inv);
}

// ---------------------------------------------------------------------------
// Kernel 3: Flash attention, fp16 MMA, fp32 accumulate. Writes g_oh (fp16).
// ---------------------------------------------------------------------------
__global__ void __launch_bounds__(256) attn_mma_kernel(const float* __restrict__ temp)
{
    __shared__ __half Qs[128 * 72];
    __shared__ __half Ks[64 * 72];
    __shared__ __half Vs[64 * 72];

    const int bh = blockIdx.y;
    const int h = bh & (HH - 1);
    const int qt = blockIdx.x;
    const int tid = threadIdx.x;
    const int w = tid >> 5;
    const int lane = tid & 31;
    const int grp = lane >> 2;
    const int qd = lane & 3;
    const float T = temp[h];

    const __half* qbase = g_qh + (size_t)bh * NT * DD;
    const __half* kbase = g_kh + (size_t)bh * NT * DD;
    const __half* vbase = g_vh + (size_t)bh * NT * DD;

#pragma unroll
    for (int it = 0; it < 4; it++) {
        int idx = it * 256 + tid;
        int r = idx >> 3;
        int c8 = (idx & 7) * 8;
        int ig = qt * 128 + r;
        int4 val = make_int4(0, 0, 0, 0);
        if (ig < NT) val = *(const int4*)(qbase + (size_t)ig * DD + c8);
        *(int4*)(Qs + r * 72 + c8) = val;
    }
    __syncthreads();

    const int rowA = (lane & 7) + (((lane >> 3) & 1) << 3);
    const int colA = (lane >> 4) << 3;
    const int rowB = (lane & 7) + ((lane >> 4) << 3);
    const int colB = ((lane >> 3) & 1) << 3;

    uint32_t aq[4][4];
    {
        const int m0 = w * 16;
#pragma unroll
        for (int ks = 0; ks < 4; ks++) {
            uint32_t addr = smem_u32(Qs + (m0 + rowA) * 72 + ks * 16 + colA);
            LDSM4(aq[ks][0], aq[ks][1], aq[ks][2], aq[ks][3], addr);
        }
    }

    float o[8][4];
#pragma unroll
    for (int c = 0; c < 8; c++)
#pragma unroll
        for (int j = 0; j < 4; j++) o[c][j] = 0.0f;
    float m0r = -1e30f, m1r = -1e30f, l0 = 0.0f, l1 = 0.0f;

    for (int kt = 0; kt < NKT; kt++) {
        __syncthreads();
#pragma unroll
        for (int it = 0; it < 2; it++) {
            int idx = it * 256 + tid;
            int r = idx >> 3;
            int c8 = (idx & 7) * 8;
            int jg = kt * 64 + r;
            int4 kv = make_int4(0, 0, 0, 0);
            int4 vv = make_int4(0, 0, 0, 0);
            if (jg < NT) {
                kv = *(const int4*)(kbase + (size_t)jg * DD + c8);
                vv = *(const int4*)(vbase + (size_t)jg * DD + c8);
            }
            *(int4*)(Ks + r * 72 + c8) = kv;
            *(int4*)(Vs + r * 72 + c8) = vv;
        }
        __syncthreads();

        float s[8][4];
#pragma unroll
        for (int c = 0; c < 8; c++)
#pragma unroll
            for (int j = 0; j < 4; j++) s[c][j] = 0.0f;

#pragma unroll
        for (int ks = 0; ks < 4; ks++) {
#pragma unroll
            for (int np = 0; np < 4; np++) {
                uint32_t b0, b1, b2, b3;
                uint32_t addr = smem_u32(Ks + (np * 16 + rowB) * 72 + ks * 16 + colB);
                LDSM4(b0, b1, b2, b3, addr);
                mma_16816(s[np * 2],     aq[ks][0], aq[ks][1], aq[ks][2], aq[ks][3], b0, b1);
                mma_16816(s[np * 2 + 1], aq[ks][0], aq[ks][1], aq[ks][2], aq[ks][3], b2, b3);
            }
        }

        const bool lastk = (kt == LASTKT);
#pragma unroll
        for (int c = 0; c < 8; c++) {
#pragma unroll
            for (int j = 0; j < 4; j++) {
                float v = s[c][j] * T;
                if (lastk && c > 0) v = -1e30f;
                s[c][j] = v;
            }
        }

        float mx0 = -1e30f, mx1 = -1e30f;
#pragma unroll
        for (int c = 0; c < 8; c++) {
            mx0 = fmaxf(mx0, fmaxf(s[c][0], s[c][1]));
            mx1 = fmaxf(mx1, fmaxf(s[c][2], s[c][3]));
        }
        mx0 = fmaxf(mx0, __shfl_xor_sync(0xffffffffu, mx0, 1));
        mx0 = fmaxf(mx0, __shfl_xor_sync(0xffffffffu, mx0, 2));
        mx1 = fmaxf(mx1, __shfl_xor_sync(0xffffffffu, mx1, 1));
        mx1 = fmaxf(mx1, __shfl_xor_sync(0xffffffffu, mx1, 2));

        float mn0 = fmaxf(m0r, mx0);
        float mn1 = fmaxf(m1r, mx1);
        float sc0 = __expf(m0r - mn0);
        float sc1 = __expf(m1r - mn1);

        float sum0 = 0.0f, sum1 = 0.0f;
        uint32_t ph0[8], ph1[8];
#pragma unroll
        for (int c = 0; c < 8; c++) {
            float p00 = __expf(s[c][0] - mn0);
            float p01 = __expf(s[c][1] - mn0);
            float p10 = __expf(s[c][2] - mn1);
            float p11 = __expf(s[c][3] - mn1);
            sum0 += p00 + p01;
            sum1 += p10 + p11;
            ph0[c] = pack_half2(p00, p01);
            ph1[c] = pack_half2(p10, p11);
        }
        sum0 += __shfl_xor_sync(0xffffffffu, sum0, 1);
        sum0 += __shfl_xor_sync(0xffffffffu, sum0, 2);
        sum1 += __shfl_xor_sync(0xffffffffu, sum1, 1);
        sum1 += __shfl_xor_sync(0xffffffffu, sum1, 2);

        l0 = l0 * sc0 + sum0;
        l1 = l1 * sc1 + sum1;
        m0r = mn0;
        m1r = mn1;
#pragma unroll
        for (int c = 0; c < 8; c++) {
            o[c][0] *= sc0; o[c][1] *= sc0;
            o[c][2] *= sc1; o[c][3] *= sc1;
        }

#pragma unroll
        for (int ks = 0; ks < 4; ks++) {
            uint32_t a0 = ph0[2 * ks], a1 = ph1[2 * ks];
            uint32_t a2 = ph0[2 * ks + 1], a3 = ph1[2 * ks + 1];
#pragma unroll
            for (int np = 0; np < 4; np++) {
                uint32_t b0, b1, b2, b3;
                uint32_t addr = smem_u32(Vs + (ks * 16 + rowA) * 72 + np * 16 + colA);
                LDSM4T(b0, b1, b2, b3, addr);
                mma_16816(o[np * 2],     a0, a1, a2, a3, b0, b1);
                mma_16816(o[np * 2 + 1], a0, a1, a2, a3, b2, b3);
            }
        }
    }

    float inv0 = 1.0f / l0;
    float inv1 = 1.0f / l1;
    int t0 = qt * 128 + w * 16 + grp;
    if (t0 < NT) {
        __half* dst = g_oh + ((size_t)bh * NT + t0) * DD;
#pragma unroll
        for (int c = 0; c < 8; c++)
            *(__half2*)(dst + c * 8 + qd * 2) =
                __floats2half2_rn(o[c][0] * inv0, o[c][1] * inv0);
    }
    int t1 = t0 + 8;
    if (t1 < NT) {
        __half* dst = g_oh + ((size_t)bh * NT + t1) * DD;
#pragma unroll
        for (int c = 0; c < 8; c++)
            *(__half2*)(dst + c * 8 + qd * 2) =
                __floats2half2_rn(o[c][2] * inv1, o[c][3] * inv1);
    }
}

// ---------------------------------------------------------------------------
// Kernel 4: output projection, fp16 MMA. A = g_oh (remapped), B = Wout.
// Tile 128x128, BK=32, double-buffered. M3 = 9216 = 72*128 exact.
// ---------------------------------------------------------------------------
__global__ void __launch_bounds__(256) out_mma_kernel(
    const float* __restrict__ Wout, float* __restrict__ out)
{
    __shared__ __half Ah[2][128][40];
    __shared__ __half Bh[2][32][136];

    const int m0 = blockIdx.y * 128;
    const int n0 = blockIdx.x * 128;
    const int tid = threadIdx.x;
    const int w = tid >> 5;
    const int lane = tid & 31;
    const int grp = lane >> 2;
    const int qd = lane & 3;
    const int wm = w >> 1;
    const int wn = w & 1;

    const int rowA = (lane & 7) + (((lane >> 3) & 1) << 3);
    const int colA = (lane >> 4) << 3;

    const int ar = tid >> 1;
    const int acs = (tid & 1) * 16;
    const int am = m0 + ar;
    const int ab = am / NQ;
    const int at = am - ab * NQ;

    const int kr = tid >> 3;
    const int bc = (tid & 7) * 16;

    int4 aPf[2];
    float4 bPf[4];

#define OUT_LOADR(kt)                                                          \
    do {                                                                       \
        int k = (kt) * 32 + acs;                                               \
        int hh2 = k >> 6;                                                      \
        int dd2 = k & 63;                                                      \
        const int4* ap4 = (const int4*)(g_oh + (((size_t)ab * HH + hh2) * NT + at) * DD + dd2); \
        aPf[0] = ap4[0]; aPf[1] = ap4[1];                                      \
        const float4* bp4 = (const float4*)(Wout + (size_t)((kt) * 32 + kr) * CDIM + n0 + bc); \
        bPf[0] = bp4[0]; bPf[1] = bp4[1]; bPf[2] = bp4[2]; bPf[3] = bp4[3];    \
    } while (0)

#define OUT_STORE(buf)                                                         \
    do {                                                                       \
        *(int4*)&Ah[buf][ar][acs]     = aPf[0];                                \
        *(int4*)&Ah[buf][ar][acs + 8] = aPf[1];                                \
        __half2 hb[8];                                                         \
        hb[0] = __floats2half2_rn(bPf[0].x, bPf[0].y);                         \
        hb[1] = __floats2half2_rn(bPf[0].z, bPf[0].w);                         \
        hb[2] = __floats2half2_rn(bPf[1].x, bPf[1].y);                         \
        hb[3] = __floats2half2_rn(bPf[1].z, bPf[1].w);                         \
        hb[4] = __floats2half2_rn(bPf[2].x, bPf[2].y);                         \
        hb[5] = __floats2half2_rn(bPf[2].z, bPf[2].w);                         \
        hb[6] = __floats2half2_rn(bPf[3].x, bPf[3].y);                         \
        hb[7] = __floats2half2_rn(bPf[3].z, bPf[3].w);                         \
        *(int4*)&Bh[buf][kr][bc]     = *(int4*)&hb[0];                         \
        *(int4*)&Bh[buf][kr][bc + 8] = *(int4*)&hb[4];                         \
    } while (0)

    float acc[2][8][4];
#pragma unroll
    for (int i = 0; i < 2; i++)
#pragma unroll
        for (int j = 0; j < 8; j++)
#pragma unroll
            for (int r = 0; r < 4; r++) acc[i][j][r] = 0.0f;

    OUT_LOADR(0);
    OUT_STORE(0);
    __syncthreads();

    for (int kt = 0; kt < 16; kt++) {
        if (kt < 15) OUT_LOADR(kt + 1);
        const int cur = kt & 1;
#pragma unroll
        for (int ks = 0; ks < 2; ks++) {
            uint32_t a[2][4];
#pragma unroll
            for (int mi = 0; mi < 2; mi++) {
                uint32_t addr = smem_u32(&Ah[cur][wm * 32 + mi * 16 + rowA][ks * 16 + colA]);
                LDSM4(a[mi][0], a[mi][1], a[mi][2], a[mi][3], addr);
            }
#pragma unroll
            for (int nc = 0; nc < 4; nc++) {
                uint32_t b0, b1, b2, b3;
                uint32_t addr = smem_u32(&Bh[cur][ks * 16 + rowA][wn * 64 + nc * 16 + colA]);
                LDSM4T(b0, b1, b2, b3, addr);
#pragma unroll
                for (int mi = 0; mi < 2; mi++) {
                    mma_16816(acc[mi][2 * nc],     a[mi][0], a[mi][1], a[mi][2], a[mi][3], b0, b1);
                    mma_16816(acc[mi][2 * nc + 1], a[mi][0], a[mi][1], a[mi][2], a[mi][3], b2, b3);
                }
            }
        }
        if (kt < 15) OUT_STORE(1 - cur);
        __syncthreads();
    }

    // Epilogue: write out fp32
#pragma unroll
    for (int mi = 0; mi < 2; mi++) {
        int rbase = m0 + wm * 32 + mi * 16 + grp;
#pragma unroll
        for (int rr = 0; rr < 2; rr++) {
            int m = rbase + rr * 8;
            int b = m / NQ;
            int t = m - b * NQ;
            float* orow = out + ((size_t)b * NQ + t) * CDIM;
#pragma unroll
            for (int nc = 0; nc < 8; nc++) {
                int c = n0 + wn * 64 + nc * 8 + qd * 2;
                *(float2*)(orow + c) =
                    make_float2(acc[mi][nc][rr * 2], acc[mi][nc][rr * 2 + 1]);
            }
        }
    }
#undef OUT_LOADR
#undef OUT_STORE
}

// ---------------------------------------------------------------------------
extern "C" void kernel_launch(void* const* d_in, const int* in_sizes, int n_in,
                              void* d_out, int out_size)
{
    const float* X    = (const float*)d_in[0];   // (4,2304,512)
    const float* S    = (const float*)d_in[1];   // (4,8,512)
    const float* Wqkv = (const float*)d_in[2];   // (512,1536)
    const float* Wout = (const float*)d_in[3];   // (512,512)
    const float* temp = (const float*)d_in[4];   // (8,1,1)
    float* out = (float*)d_out;                  // (4,2304,512)

    // 1. QKV GEMM (tensor core)
    {
        dim3 grid(1536 / 128, (M1 + 127) / 128);   // (12, 73)
        qkv_mma_kernel<<<grid, 256>>>(X, S, Wqkv);
    }
    // 2. L2 normalize q,k -> fp16
    {
        int rows = 2 * BB * HH * NT;
        int blocks = (rows + 7) / 8;
        l2norm_kernel<<<blocks, 256>>>();
    }
    // 3. Attention (tensor core)
    {
        dim3 grid(NQT, BB * HH);                   // (19, 32)
        attn_mma_kernel<<<grid, 256>>>(temp);
    }
    // 4. Output projection (tensor core)
    {
        dim3 grid(CDIM / 128, M3 / 128);           // (4, 72)
        out_mma_kernel<<<grid, 256>>>(Wout, out);
    }
}

// round 7
// speedup vs baseline: 6.1036x; 1.2241x over previous
#include <cuda_runtime.h>
#include <cuda_fp16.h>
#include <cuda_bf16.h>
#include <math.h>
#include <stdint.h>

#define BB 4
#define NQ 2304
#define NT 2312           // NQ + 8 summary tokens
#define CDIM 512
#define HH 8
#define DD 64
#define M1 (BB * NT)      // 9248
#define M3 (BB * NQ)      // 9216
#define QKV_ELEMS (BB * HH * NT * DD)   // 4,734,976
#define NKT 37            // ceil(NT/64) key tiles
#define LASTKT 36
#define NQT 19            // ceil(NT/128) query tiles
#define KVT (64 * 72)     // one K or V buffer in halves

// Scratch (no allocations allowed)
__device__ __half g_xh[M1 * CDIM];        // concat(X,S) fp16
__device__ __half g_wqkvh[CDIM * 1536];   // Wqkv fp16
__device__ __half g_wouth[CDIM * CDIM];   // Wout fp16
__device__ __half g_qh[QKV_ELEMS];        // normalized q fp16
__device__ __half g_kh[QKV_ELEMS];        // normalized k fp16
__device__ __half g_vh[QKV_ELEMS];        // v fp16
__device__ __half g_oh[QKV_ELEMS];        // attention output fp16

// ---------------------------------------------------------------------------
// helpers
// ---------------------------------------------------------------------------
static __device__ __forceinline__ uint32_t smem_u32(const void* p) {
    return (uint32_t)__cvta_generic_to_shared(p);
}

#define LDSM4(r0, r1, r2, r3, addr)                                            \
    asm volatile("ldmatrix.sync.aligned.m8n8.x4.shared.b16 {%0,%1,%2,%3}, [%4];" \
                 : "=r"(r0), "=r"(r1), "=r"(r2), "=r"(r3) : "r"(addr))

#define LDSM4T(r0, r1, r2, r3, addr)                                           \
    asm volatile("ldmatrix.sync.aligned.m8n8.x4.trans.shared.b16 {%0,%1,%2,%3}, [%4];" \
                 : "=r"(r0), "=r"(r1), "=r"(r2), "=r"(r3) : "r"(addr))

static __device__ __forceinline__ void mma_16816(
    float c[4], uint32_t a0, uint32_t a1, uint32_t a2, uint32_t a3,
    uint32_t b0, uint32_t b1)
{
    asm volatile(
        "mma.sync.aligned.m16n8k16.row.col.f32.f16.f16.f32 "
        "{%0,%1,%2,%3},{%4,%5,%6,%7},{%8,%9},{%0,%1,%2,%3};"
        : "+f"(c[0]), "+f"(c[1]), "+f"(c[2]), "+f"(c[3])
        : "r"(a0), "r"(a1), "r"(a2), "r"(a3), "r"(b0), "r"(b1));
}

static __device__ __forceinline__ uint32_t pack_half2(float x, float y) {
    __half2 h = __floats2half2_rn(x, y);
    return reinterpret_cast<uint32_t&>(h);
}

#define CP_A16(dst, src, valid)                                                \
    asm volatile("cp.async.ca.shared.global [%0], [%1], 16, %2;"               \
                 :: "r"(dst), "l"(src), "r"((valid) ? 16 : 0))
#define CP_COMMIT() asm volatile("cp.async.commit_group;")
#define CP_WAIT1()  asm volatile("cp.async.wait_group 1;")
#define CP_WAIT0()  asm volatile("cp.async.wait_group 0;")

// ---------------------------------------------------------------------------
// Kernel 0: fp32 -> fp16 conversion of inputs (concat X,S) and weights.
// One float4 per thread.
// ---------------------------------------------------------------------------
#define CVT_A   (M1 * CDIM / 4)             // 1183744
#define CVT_WQ  (CDIM * 1536 / 4)           // 196608
#define CVT_WO  (CDIM * CDIM / 4)           // 65536
#define CVT_TOT (CVT_A + CVT_WQ + CVT_WO)   // 1445888

__global__ void __launch_bounds__(256) convert_kernel(
    const float* __restrict__ X, const float* __restrict__ S,
    const float* __restrict__ Wq, const float* __restrict__ Wo)
{
    int i = blockIdx.x * 256 + threadIdx.x;
    if (i >= CVT_TOT) return;
    const float* src;
    __half* dst;
    if (i < CVT_A) {
        int row = i >> 7;
        int c4 = (i & 127) * 4;
        int b = row / NT;
        int t = row - b * NT;
        src = (t < NQ) ? X + ((size_t)b * NQ + t) * CDIM + c4
                       : S + ((size_t)b * 8 + (t - NQ)) * CDIM + c4;
        dst = g_xh + (size_t)row * CDIM + c4;
    } else if (i < CVT_A + CVT_WQ) {
        int j = (i - CVT_A) * 4;
        src = Wq + j;
        dst = g_wqkvh + j;
    } else {
        int j = (i - CVT_A - CVT_WQ) * 4;
        src = Wo + j;
        dst = g_wouth + j;
    }
    float4 v = *(const float4*)src;
    __half2 h0 = __floats2half2_rn(v.x, v.y);
    __half2 h1 = __floats2half2_rn(v.z, v.w);
    uint2 u;
    u.x = reinterpret_cast<uint32_t&>(h0);
    u.y = reinterpret_cast<uint32_t&>(h1);
    *(uint2*)dst = u;
}

// ---------------------------------------------------------------------------
// Kernel 1: QKV GEMM, fp16 MMA + cp.async double buffer.
// A = g_xh (M1 x 512), B = g_wqkvh (512 x 1536). Tile 128x128x32.
// Epilogue: fused L2-norm for q,k (quad reduction) -> g_qh/g_kh; v -> g_vh.
// ---------------------------------------------------------------------------
__global__ void __launch_bounds__(256) qkv_mma_kernel()
{
    __shared__ __half Ah[2][128][40];
    __shared__ __half Bh[2][32][136];

    const int m0 = blockIdx.y * 128;
    const int n0 = blockIdx.x * 128;
    const int tid = threadIdx.x;
    const int w = tid >> 5;
    const int lane = tid & 31;
    const int grp = lane >> 2;
    const int qd = lane & 3;
    const int wm = w >> 1;
    const int wn = w & 1;

    const int rowA = (lane & 7) + (((lane >> 3) & 1) << 3);
    const int colA = (lane >> 4) << 3;

    const int ar = tid >> 1;
    const int ac = (tid & 1) * 16;
    const bool aok = (m0 + ar) < M1;
    const int kr = tid >> 3;
    const int bc = (tid & 7) * 16;

#define QKV_PREF(kt, buf)                                                      \
    do {                                                                       \
        uint32_t ad = smem_u32(&Ah[buf][ar][ac]);                              \
        const __half* ag = g_xh + (size_t)(m0 + ar) * CDIM + (kt) * 32 + ac;   \
        CP_A16(ad, ag, aok);                                                   \
        CP_A16(ad + 16, ag + 8, aok);                                          \
        uint32_t bd = smem_u32(&Bh[buf][kr][bc]);                              \
        const __half* bg = g_wqkvh + (size_t)((kt) * 32 + kr) * 1536 + n0 + bc;\
        CP_A16(bd, bg, true);                                                  \
        CP_A16(bd + 16, bg + 8, true);                                         \
    } while (0)

    float acc[2][8][4];
#pragma unroll
    for (int i = 0; i < 2; i++)
#pragma unroll
        for (int j = 0; j < 8; j++)
#pragma unroll
            for (int r = 0; r < 4; r++) acc[i][j][r] = 0.0f;

    QKV_PREF(0, 0);
    CP_COMMIT();

    for (int kt = 0; kt < 16; kt++) {
        const int cur = kt & 1;
        if (kt < 15) {
            QKV_PREF(kt + 1, 1 - cur);
            CP_COMMIT();
            CP_WAIT1();
        } else {
            CP_WAIT0();
        }
        __syncthreads();
#pragma unroll
        for (int ks = 0; ks < 2; ks++) {
            uint32_t a[2][4];
#pragma unroll
            for (int mi = 0; mi < 2; mi++) {
                uint32_t addr = smem_u32(&Ah[cur][wm * 32 + mi * 16 + rowA][ks * 16 + colA]);
                LDSM4(a[mi][0], a[mi][1], a[mi][2], a[mi][3], addr);
            }
#pragma unroll
            for (int nc = 0; nc < 4; nc++) {
                uint32_t b0, b1, b2, b3;
                uint32_t addr = smem_u32(&Bh[cur][ks * 16 + rowA][wn * 64 + nc * 16 + colA]);
                LDSM4T(b0, b1, b2, b3, addr);
#pragma unroll
                for (int mi = 0; mi < 2; mi++) {
                    mma_16816(acc[mi][2 * nc],     a[mi][0], a[mi][1], a[mi][2], a[mi][3], b0, b1);
                    mma_16816(acc[mi][2 * nc + 1], a[mi][0], a[mi][1], a[mi][2], a[mi][3], b2, b3);
                }
            }
        }
        __syncthreads();
    }
#undef QKV_PREF

    // Epilogue. This warp's 64 columns = one head of one of q/k/v.
    const int cbase = n0 + wn * 64;
    const int which = cbase >> 9;          // 0=q 1=k 2=v (uniform per warp)
    const int h = (cbase >> 6) & 7;
    __half* dstbase = (which == 0) ? g_qh : (which == 1) ? g_kh : g_vh;

#pragma unroll
    for (int mi = 0; mi < 2; mi++) {
#pragma unroll
        for (int rr = 0; rr < 2; rr++) {
            int m = m0 + wm * 32 + mi * 16 + rr * 8 + grp;
            float inv = 1.0f;
            if (which < 2) {
                float ss = 0.0f;
#pragma unroll
                for (int nc = 0; nc < 8; nc++) {
                    float a0 = acc[mi][nc][rr * 2];
                    float a1 = acc[mi][nc][rr * 2 + 1];
                    ss += a0 * a0 + a1 * a1;
                }
                ss += __shfl_xor_sync(0xffffffffu, ss, 1);
                ss += __shfl_xor_sync(0xffffffffu, ss, 2);
                inv = 1.0f / fmaxf(sqrtf(ss), 1e-12f);
            }
            if (m < M1) {
                int b = m / NT;
                int t = m - b * NT;
                __half* dst = dstbase + (((size_t)b * HH + h) * NT + t) * DD;
#pragma unroll
                for (int nc = 0; nc < 8; nc++) {
                    *(__half2*)(dst + nc * 8 + qd * 2) = __floats2half2_rn(
                        acc[mi][nc][rr * 2] * inv, acc[mi][nc][rr * 2 + 1] * inv);
                }
            }
        }
    }
}

// ---------------------------------------------------------------------------
// Kernel 2: Flash attention, fp16 MMA + cp.async double-buffered K/V.
// Dynamic smem: Q[128*72], K[2][64*72], V[2][64*72] halves = 55296 B.
// ---------------------------------------------------------------------------
__global__ void __launch_bounds__(256) attn_mma_kernel(const float* __restrict__ temp)
{
    extern __shared__ __half dynsm[];
    __half* Qs  = dynsm;                   // 128*72
    __half* Ksb = dynsm + 128 * 72;        // 2 * KVT
    __half* Vsb = Ksb + 2 * KVT;           // 2 * KVT

    const int bh = blockIdx.y;
    const int h = bh & (HH - 1);
    const int qt = blockIdx.x;
    const int tid = threadIdx.x;
    const int w = tid >> 5;
    const int lane = tid & 31;
    const int grp = lane >> 2;
    const int qd = lane & 3;
    const float T = temp[h];

    const __half* qbase = g_qh + (size_t)bh * NT * DD;
    const __half* kbase = g_kh + (size_t)bh * NT * DD;
    const __half* vbase = g_vh + (size_t)bh * NT * DD;

    const int r_ = tid >> 2;           // 0..63
    const int cc_ = (tid & 3) * 16;    // 0,16,32,48

#define ATT_PREF(kt, buf)                                                      \
    do {                                                                       \
        int jg = (kt) * 64 + r_;                                               \
        bool v = jg < NT;                                                      \
        const __half* kg = kbase + (size_t)jg * DD + cc_;                      \
        const __half* vg = vbase + (size_t)jg * DD + cc_;                      \
        uint32_t kd = smem_u32(Ksb + (buf) * KVT + r_ * 72 + cc_);             \
        uint32_t vd = smem_u32(Vsb + (buf) * KVT + r_ * 72 + cc_);             \
        CP_A16(kd, kg, v); CP_A16(kd + 16, kg + 8, v);                         \
        CP_A16(vd, vg, v); CP_A16(vd + 16, vg + 8, v);                         \
    } while (0)

    // stage Q + first K/V prefetch
    ATT_PREF(0, 0);
    CP_COMMIT();
#pragma unroll
    for (int it = 0; it < 4; it++) {
        int idx = it * 256 + tid;
        int r = idx >> 3;
        int c8 = (idx & 7) * 8;
        int ig = qt * 128 + r;
        int4 val = make_int4(0, 0, 0, 0);
        if (ig < NT) val = *(const int4*)(qbase + (size_t)ig * DD + c8);
        *(int4*)(Qs + r * 72 + c8) = val;
    }
    __syncthreads();

    const int rowA = (lane & 7) + (((lane >> 3) & 1) << 3);
    const int colA = (lane >> 4) << 3;
    const int rowB = (lane & 7) + ((lane >> 4) << 3);
    const int colB = ((lane >> 3) & 1) << 3;

    uint32_t aq[4][4];
    {
        const int m0 = w * 16;
#pragma unroll
        for (int ks = 0; ks < 4; ks++) {
            uint32_t addr = smem_u32(Qs + (m0 + rowA) * 72 + ks * 16 + colA);
            LDSM4(aq[ks][0], aq[ks][1], aq[ks][2], aq[ks][3], addr);
        }
    }

    float o[8][4];
#pragma unroll
    for (int c = 0; c < 8; c++)
#pragma unroll
        for (int j = 0; j < 4; j++) o[c][j] = 0.0f;
    float m0r = -1e30f, m1r = -1e30f, l0 = 0.0f, l1 = 0.0f;

    for (int kt = 0; kt < NKT; kt++) {
        const int cur = kt & 1;
        if (kt < NKT - 1) {
            ATT_PREF(kt + 1, 1 - cur);
            CP_COMMIT();
            CP_WAIT1();
        } else {
            CP_WAIT0();
        }
        __syncthreads();

        const __half* Ks = Ksb + cur * KVT;
        const __half* Vs = Vsb + cur * KVT;

        float s[8][4];
#pragma unroll
        for (int c = 0; c < 8; c++)
#pragma unroll
            for (int j = 0; j < 4; j++) s[c][j] = 0.0f;

#pragma unroll
        for (int ks = 0; ks < 4; ks++) {
#pragma unroll
            for (int np = 0; np < 4; np++) {
                uint32_t b0, b1, b2, b3;
                uint32_t addr = smem_u32(Ks + (np * 16 + rowB) * 72 + ks * 16 + colB);
                LDSM4(b0, b1, b2, b3, addr);
                mma_16816(s[np * 2],     aq[ks][0], aq[ks][1], aq[ks][2], aq[ks][3], b0, b1);
                mma_16816(s[np * 2 + 1], aq[ks][0], aq[ks][1], aq[ks][2], aq[ks][3], b2, b3);
            }
        }

        const bool lastk = (kt == LASTKT);
#pragma unroll
        for (int c = 0; c < 8; c++) {
#pragma unroll
            for (int j = 0; j < 4; j++) {
                float v = s[c][j] * T;
                if (lastk && c > 0) v = -1e30f;
                s[c][j] = v;
            }
        }

        float mx0 = -1e30f, mx1 = -1e30f;
#pragma unroll
        for (int c = 0; c < 8; c++) {
            mx0 = fmaxf(mx0, fmaxf(s[c][0], s[c][1]));
            mx1 = fmaxf(mx1, fmaxf(s[c][2], s[c][3]));
        }
        mx0 = fmaxf(mx0, __shfl_xor_sync(0xffffffffu, mx0, 1));
        mx0 = fmaxf(mx0, __shfl_xor_sync(0xffffffffu, mx0, 2));
        mx1 = fmaxf(mx1, __shfl_xor_sync(0xffffffffu, mx1, 1));
        mx1 = fmaxf(mx1, __shfl_xor_sync(0xffffffffu, mx1, 2));

        float mn0 = fmaxf(m0r, mx0);
        float mn1 = fmaxf(m1r, mx1);
        float sc0 = __expf(m0r - mn0);
        float sc1 = __expf(m1r - mn1);

        float sum0 = 0.0f, sum1 = 0.0f;
        uint32_t ph0[8], ph1[8];
#pragma unroll
        for (int c = 0; c < 8; c++) {
            float p00 = __expf(s[c][0] - mn0);
            float p01 = __expf(s[c][1] - mn0);
            float p10 = __expf(s[c][2] - mn1);
            float p11 = __expf(s[c][3] - mn1);
            sum0 += p00 + p01;
            sum1 += p10 + p11;
            ph0[c] = pack_half2(p00, p01);
            ph1[c] = pack_half2(p10, p11);
        }
        sum0 += __shfl_xor_sync(0xffffffffu, sum0, 1);
        sum0 += __shfl_xor_sync(0xffffffffu, sum0, 2);
        sum1 += __shfl_xor_sync(0xffffffffu, sum1, 1);
        sum1 += __shfl_xor_sync(0xffffffffu, sum1, 2);

        l0 = l0 * sc0 + sum0;
        l1 = l1 * sc1 + sum1;
        m0r = mn0;
        m1r = mn1;
#pragma unroll
        for (int c = 0; c < 8; c++) {
            o[c][0] *= sc0; o[c][1] *= sc0;
            o[c][2] *= sc1; o[c][3] *= sc1;
        }

#pragma unroll
        for (int ks = 0; ks < 4; ks++) {
            uint32_t a0 = ph0[2 * ks], a1 = ph1[2 * ks];
            uint32_t a2 = ph0[2 * ks + 1], a3 = ph1[2 * ks + 1];
#pragma unroll
            for (int np = 0; np < 4; np++) {
                uint32_t b0, b1, b2, b3;
                uint32_t addr = smem_u32(Vs + (ks * 16 + rowA) * 72 + np * 16 + colA);
                LDSM4T(b0, b1, b2, b3, addr);
                mma_16816(o[np * 2],     a0, a1, a2, a3, b0, b1);
                mma_16816(o[np * 2 + 1], a0, a1, a2, a3, b2, b3);
            }
        }
        __syncthreads();
    }
#undef ATT_PREF

    float inv0 = 1.0f / l0;
    float inv1 = 1.0f / l1;
    int t0 = qt * 128 + w * 16 + grp;
    if (t0 < NT) {
        __half* dst = g_oh + ((size_t)bh * NT + t0) * DD;
#pragma unroll
        for (int c = 0; c < 8; c++)
            *(__half2*)(dst + c * 8 + qd * 2) =
                __floats2half2_rn(o[c][0] * inv0, o[c][1] * inv0);
    }
    int t1 = t0 + 8;
    if (t1 < NT) {
        __half* dst = g_oh + ((size_t)bh * NT + t1) * DD;
#pragma unroll
        for (int c = 0; c < 8; c++)
            *(__half2*)(dst + c * 8 + qd * 2) =
                __floats2half2_rn(o[c][2] * inv1, o[c][3] * inv1);
    }
}

// ---------------------------------------------------------------------------
// Kernel 3: output projection, fp16 MMA + cp.async. A = g_oh remap, B = g_wouth.
// ---------------------------------------------------------------------------
__global__ void __launch_bounds__(256) out_mma_kernel(float* __restrict__ out)
{
    __shared__ __half Ah[2][128][40];
    __shared__ __half Bh[2][32][136];

    const int m0 = blockIdx.y * 128;
    const int n0 = blockIdx.x * 128;
    const int tid = threadIdx.x;
    const int w = tid >> 5;
    const int lane = tid & 31;
    const int grp = lane >> 2;
    const int qd = lane & 3;
    const int wm = w >> 1;
    const int wn = w & 1;

    const int rowA = (lane & 7) + (((lane >> 3) & 1) << 3);
    const int colA = (lane >> 4) << 3;

    const int ar = tid >> 1;
    const int ac = (tid & 1) * 16;
    const int am = m0 + ar;
    const int ab = am / NQ;
    const int at = am - ab * NQ;
    const int kr = tid >> 3;
    const int bc = (tid & 7) * 16;

#define OUT_PREF(kt, buf)                                                      \
    do {                                                                       \
        int k = (kt) * 32 + ac;                                                \
        int hh2 = k >> 6;                                                      \
        int dd2 = k & 63;                                                      \
        uint32_t ad = smem_u32(&Ah[buf][ar][ac]);                              \
        const __half* ag = g_oh + (((size_t)ab * HH + hh2) * NT + at) * DD + dd2; \
        CP_A16(ad, ag, true);                                                  \
        CP_A16(ad + 16, ag + 8, true);                                         \
        uint32_t bd = smem_u32(&Bh[buf][kr][bc]);                              \
        const __half* bg = g_wouth + (size_t)((kt) * 32 + kr) * CDIM + n0 + bc;\
        CP_A16(bd, bg, true);                                                  \
        CP_A16(bd + 16, bg + 8, true);                                         \
    } while (0)

    float acc[2][8][4];
#pragma unroll
    for (int i = 0; i < 2; i++)
#pragma unroll
        for (int j = 0; j < 8; j++)
#pragma unroll
            for (int r = 0; r < 4; r++) acc[i][j][r] = 0.0f;

    OUT_PREF(0, 0);
    CP_COMMIT();

    for (int kt = 0; kt < 16; kt++) {
        const int cur = kt & 1;
        if (kt < 15) {
            OUT_PREF(kt + 1, 1 - cur);
            CP_COMMIT();
            CP_WAIT1();
        } else {
            CP_WAIT0();
        }
        __syncthreads();
#pragma unroll
        for (int ks = 0; ks < 2; ks++) {
            uint32_t a[2][4];
#pragma unroll
            for (int mi = 0; mi < 2; mi++) {
                uint32_t addr = smem_u32(&Ah[cur][wm * 32 + mi * 16 + rowA][ks * 16 + colA]);
                LDSM4(a[mi][0], a[mi][1], a[mi][2], a[mi][3], addr);
            }
#pragma unroll
            for (int nc = 0; nc < 4; nc++) {
                uint32_t b0, b1, b2, b3;
                uint32_t addr = smem_u32(&Bh[cur][ks * 16 + rowA][wn * 64 + nc * 16 + colA]);
                LDSM4T(b0, b1, b2, b3, addr);
#pragma unroll
                for (int mi = 0; mi < 2; mi++) {
                    mma_16816(acc[mi][2 * nc],     a[mi][0], a[mi][1], a[mi][2], a[mi][3], b0, b1);
                    mma_16816(acc[mi][2 * nc + 1], a[mi][0], a[mi][1], a[mi][2], a[mi][3], b2, b3);
                }
            }
        }
        __syncthreads();
    }
#undef OUT_PREF

#pragma unroll
    for (int mi = 0; mi < 2; mi++) {
        int rbase = m0 + wm * 32 + mi * 16 + grp;
#pragma unroll
        for (int rr = 0; rr < 2; rr++) {
            int m = rbase + rr * 8;
            int b = m / NQ;
            int t = m - b * NQ;
            float* orow = out + ((size_t)b * NQ + t) * CDIM;
#pragma unroll
            for (int nc = 0; nc < 8; nc++) {
                int c = n0 + wn * 64 + nc * 8 + qd * 2;
                *(float2*)(orow + c) =
                    make_float2(acc[mi][nc][rr * 2], acc[mi][nc][rr * 2 + 1]);
            }
        }
    }
}

// ---------------------------------------------------------------------------
extern "C" void kernel_launch(void* const* d_in, const int* in_sizes, int n_in,
                              void* d_out, int out_size)
{
    const float* X    = (const float*)d_in[0];   // (4,2304,512)
    const float* S    = (const float*)d_in[1];   // (4,8,512)
    const float* Wqkv = (const float*)d_in[2];   // (512,1536)
    const float* Wout = (const float*)d_in[3];   // (512,512)
    const float* temp = (const float*)d_in[4];   // (8,1,1)
    float* out = (float*)d_out;                  // (4,2304,512)

    // 0. fp32 -> fp16 conversion
    {
        int blocks = (CVT_TOT + 255) / 256;
        convert_kernel<<<blocks, 256>>>(X, S, Wqkv, Wout);
    }
    // 1. QKV GEMM + fused l2norm epilogue
    {
        dim3 grid(1536 / 128, (M1 + 127) / 128);   // (12, 73)
        qkv_mma_kernel<<<grid, 256>>>();
    }
    // 2. Attention
    {
        size_t smem = (128 * 72 + 4 * KVT) * sizeof(__half);   // 55296 B
        (void)cudaFuncSetAttribute(attn_mma_kernel,
                                   cudaFuncAttributeMaxDynamicSharedMemorySize,
                                   (int)smem);
        dim3 grid(NQT, BB * HH);                   // (19, 32)
        attn_mma_kernel<<<grid, 256, smem>>>(temp);
    }
    // 3. Output projection
    {
        dim3 grid(CDIM / 128, M3 / 128);           // (4, 72)
        out_mma_kernel<<<grid, 256>>>(out);
    }
}

// round 8
// speedup vs baseline: 6.2642x; 1.0263x over previous
#include <cuda_runtime.h>
#include <cuda_fp16.h>
#include <cuda_bf16.h>
#include <math.h>
#include <stdint.h>

#define BB 4
#define NQ 2304
#define NT 2312           // NQ + 8 summary tokens
#define CDIM 512
#define HH 8
#define DD 64
#define M1 (BB * NT)      // 9248
#define M3 (BB * NQ)      // 9216
#define QKV_ELEMS (BB * HH * NT * DD)   // 4,734,976
#define NKT 37            // ceil(NT/64) key tiles
#define LASTKT 36
#define NQT 19            // ceil(NT/128) query tiles
#define KVT (64 * 72)     // one K or V buffer in halves

// Scratch (no allocations allowed)
__device__ __half g_xh[M1 * CDIM];        // concat(X,S) fp16
__device__ __half g_wqkvh[CDIM * 1536];   // Wqkv fp16
__device__ __half g_wouth[CDIM * CDIM];   // Wout fp16
__device__ __half g_qh[QKV_ELEMS];        // normalized q fp16
__device__ __half g_kh[QKV_ELEMS];        // normalized k fp16
__device__ __half g_vh[QKV_ELEMS];        // v fp16
__device__ __half g_oh[QKV_ELEMS];        // attention output fp16

// ---------------------------------------------------------------------------
// helpers
// ---------------------------------------------------------------------------
static __device__ __forceinline__ uint32_t smem_u32(const void* p) {
    return (uint32_t)__cvta_generic_to_shared(p);
}

#define LDSM4(r0, r1, r2, r3, addr)                                            \
    asm volatile("ldmatrix.sync.aligned.m8n8.x4.shared.b16 {%0,%1,%2,%3}, [%4];" \
                 : "=r"(r0), "=r"(r1), "=r"(r2), "=r"(r3) : "r"(addr))

#define LDSM4T(r0, r1, r2, r3, addr)                                           \
    asm volatile("ldmatrix.sync.aligned.m8n8.x4.trans.shared.b16 {%0,%1,%2,%3}, [%4];" \
                 : "=r"(r0), "=r"(r1), "=r"(r2), "=r"(r3) : "r"(addr))

static __device__ __forceinline__ void mma_16816(
    float c[4], uint32_t a0, uint32_t a1, uint32_t a2, uint32_t a3,
    uint32_t b0, uint32_t b1)
{
    asm volatile(
        "mma.sync.aligned.m16n8k16.row.col.f32.f16.f16.f32 "
        "{%0,%1,%2,%3},{%4,%5,%6,%7},{%8,%9},{%0,%1,%2,%3};"
        : "+f"(c[0]), "+f"(c[1]), "+f"(c[2]), "+f"(c[3])
        : "r"(a0), "r"(a1), "r"(a2), "r"(a3), "r"(b0), "r"(b1));
}

static __device__ __forceinline__ uint32_t pack_half2(float x, float y) {
    __half2 h = __floats2half2_rn(x, y);
    return reinterpret_cast<uint32_t&>(h);
}

static __device__ __forceinline__ float ex2(float x) {
    float r;
    asm("ex2.approx.f32 %0, %1;" : "=f"(r) : "f"(x));
    return r;
}

#define CP_A16(dst, src, valid)                                                \
    asm volatile("cp.async.ca.shared.global [%0], [%1], 16, %2;"               \
                 :: "r"(dst), "l"(src), "r"((valid) ? 16 : 0))
#define CP_COMMIT() asm volatile("cp.async.commit_group;")
#define CP_WAIT1()  asm volatile("cp.async.wait_group 1;")
#define CP_WAIT0()  asm volatile("cp.async.wait_group 0;")

// ---------------------------------------------------------------------------
// Kernel 0: fp32 -> fp16 conversion of inputs (concat X,S) and weights.
// ---------------------------------------------------------------------------
#define CVT_A   (M1 * CDIM / 4)             // 1183744
#define CVT_WQ  (CDIM * 1536 / 4)           // 196608
#define CVT_WO  (CDIM * CDIM / 4)           // 65536
#define CVT_TOT (CVT_A + CVT_WQ + CVT_WO)   // 1445888

__global__ void __launch_bounds__(256) convert_kernel(
    const float* __restrict__ X, const float* __restrict__ S,
    const float* __restrict__ Wq, const float* __restrict__ Wo)
{
    int i = blockIdx.x * 256 + threadIdx.x;
    if (i >= CVT_TOT) return;
    const float* src;
    __half* dst;
    if (i < CVT_A) {
        int row = i >> 7;
        int c4 = (i & 127) * 4;
        int b = row / NT;
        int t = row - b * NT;
        src = (t < NQ) ? X + ((size_t)b * NQ + t) * CDIM + c4
                       : S + ((size_t)b * 8 + (t - NQ)) * CDIM + c4;
        dst = g_xh + (size_t)row * CDIM + c4;
    } else if (i < CVT_A + CVT_WQ) {
        int j = (i - CVT_A) * 4;
        src = Wq + j;
        dst = g_wqkvh + j;
    } else {
        int j = (i - CVT_A - CVT_WQ) * 4;
        src = Wo + j;
        dst = g_wouth + j;
    }
    float4 v = *(const float4*)src;
    __half2 h0 = __floats2half2_rn(v.x, v.y);
    __half2 h1 = __floats2half2_rn(v.z, v.w);
    uint2 u;
    u.x = reinterpret_cast<uint32_t&>(h0);
    u.y = reinterpret_cast<uint32_t&>(h1);
    *(uint2*)dst = u;
}

// ---------------------------------------------------------------------------
// Kernel 1: QKV GEMM, fp16 MMA + cp.async double buffer. 2 CTAs/SM.
// ---------------------------------------------------------------------------
__global__ void __launch_bounds__(256, 2) qkv_mma_kernel()
{
    __shared__ __half Ah[2][128][40];
    __shared__ __half Bh[2][32][136];

    const int m0 = blockIdx.y * 128;
    const int n0 = blockIdx.x * 128;
    const int tid = threadIdx.x;
    const int w = tid >> 5;
    const int lane = tid & 31;
    const int grp = lane >> 2;
    const int qd = lane & 3;
    const int wm = w >> 1;
    const int wn = w & 1;

    const int rowA = (lane & 7) + (((lane >> 3) & 1) << 3);
    const int colA = (lane >> 4) << 3;

    const int ar = tid >> 1;
    const int ac = (tid & 1) * 16;
    const bool aok = (m0 + ar) < M1;
    const int kr = tid >> 3;
    const int bc = (tid & 7) * 16;

#define QKV_PREF(kt, buf)                                                      \
    do {                                                                       \
        uint32_t ad = smem_u32(&Ah[buf][ar][ac]);                              \
        const __half* ag = g_xh + (size_t)(m0 + ar) * CDIM + (kt) * 32 + ac;   \
        CP_A16(ad, ag, aok);                                                   \
        CP_A16(ad + 16, ag + 8, aok);                                          \
        uint32_t bd = smem_u32(&Bh[buf][kr][bc]);                              \
        const __half* bg = g_wqkvh + (size_t)((kt) * 32 + kr) * 1536 + n0 + bc;\
        CP_A16(bd, bg, true);                                                  \
        CP_A16(bd + 16, bg + 8, true);                                         \
    } while (0)

    float acc[2][8][4];
#pragma unroll
    for (int i = 0; i < 2; i++)
#pragma unroll
        for (int j = 0; j < 8; j++)
#pragma unroll
            for (int r = 0; r < 4; r++) acc[i][j][r] = 0.0f;

    QKV_PREF(0, 0);
    CP_COMMIT();

    for (int kt = 0; kt < 16; kt++) {
        const int cur = kt & 1;
        if (kt < 15) {
            QKV_PREF(kt + 1, 1 - cur);
            CP_COMMIT();
            CP_WAIT1();
        } else {
            CP_WAIT0();
        }
        __syncthreads();
#pragma unroll
        for (int ks = 0; ks < 2; ks++) {
            uint32_t a[2][4];
#pragma unroll
            for (int mi = 0; mi < 2; mi++) {
                uint32_t addr = smem_u32(&Ah[cur][wm * 32 + mi * 16 + rowA][ks * 16 + colA]);
                LDSM4(a[mi][0], a[mi][1], a[mi][2], a[mi][3], addr);
            }
#pragma unroll
            for (int nc = 0; nc < 4; nc++) {
                uint32_t b0, b1, b2, b3;
                uint32_t addr = smem_u32(&Bh[cur][ks * 16 + rowA][wn * 64 + nc * 16 + colA]);
                LDSM4T(b0, b1, b2, b3, addr);
#pragma unroll
                for (int mi = 0; mi < 2; mi++) {
                    mma_16816(acc[mi][2 * nc],     a[mi][0], a[mi][1], a[mi][2], a[mi][3], b0, b1);
                    mma_16816(acc[mi][2 * nc + 1], a[mi][0], a[mi][1], a[mi][2], a[mi][3], b2, b3);
                }
            }
        }
        __syncthreads();
    }
#undef QKV_PREF

    // Epilogue. This warp's 64 columns = one head of one of q/k/v.
    const int cbase = n0 + wn * 64;
    const int which = cbase >> 9;          // 0=q 1=k 2=v (uniform per warp)
    const int h = (cbase >> 6) & 7;
    __half* dstbase = (which == 0) ? g_qh : (which == 1) ? g_kh : g_vh;

#pragma unroll
    for (int mi = 0; mi < 2; mi++) {
#pragma unroll
        for (int rr = 0; rr < 2; rr++) {
            int m = m0 + wm * 32 + mi * 16 + rr * 8 + grp;
            float inv = 1.0f;
            if (which < 2) {
                float ss = 0.0f;
#pragma unroll
                for (int nc = 0; nc < 8; nc++) {
                    float a0 = acc[mi][nc][rr * 2];
                    float a1 = acc[mi][nc][rr * 2 + 1];
                    ss += a0 * a0 + a1 * a1;
                }
                ss += __shfl_xor_sync(0xffffffffu, ss, 1);
                ss += __shfl_xor_sync(0xffffffffu, ss, 2);
                inv = 1.0f / fmaxf(sqrtf(ss), 1e-12f);
            }
            if (m < M1) {
                int b = m / NT;
                int t = m - b * NT;
                __half* dst = dstbase + (((size_t)b * HH + h) * NT + t) * DD;
#pragma unroll
                for (int nc = 0; nc < 8; nc++) {
                    *(__half2*)(dst + nc * 8 + qd * 2) = __floats2half2_rn(
                        acc[mi][nc][rr * 2] * inv, acc[mi][nc][rr * 2 + 1] * inv);
                }
            }
        }
    }
}

// ---------------------------------------------------------------------------
// Kernel 2: Flash attention, fp16 MMA + cp.async double-buffered K/V.
// 2 CTAs/SM, base-2 softmax.
// ---------------------------------------------------------------------------
__global__ void __launch_bounds__(256, 2) attn_mma_kernel(const float* __restrict__ temp)
{
    extern __shared__ __half dynsm[];
    __half* Qs  = dynsm;                   // 128*72
    __half* Ksb = dynsm + 128 * 72;        // 2 * KVT
    __half* Vsb = Ksb + 2 * KVT;           // 2 * KVT

    const int bh = blockIdx.y;
    const int h = bh & (HH - 1);
    const int qt = blockIdx.x;
    const int tid = threadIdx.x;
    const int w = tid >> 5;
    const int lane = tid & 31;
    const int grp = lane >> 2;
    const int qd = lane & 3;
    const float T2 = temp[h] * 1.44269504089f;   // base-2 scale

    const __half* qbase = g_qh + (size_t)bh * NT * DD;
    const __half* kbase = g_kh + (size_t)bh * NT * DD;
    const __half* vbase = g_vh + (size_t)bh * NT * DD;

    const int r_ = tid >> 2;           // 0..63
    const int cc_ = (tid & 3) * 16;    // 0,16,32,48

#define ATT_PREF(kt, buf)                                                      \
    do {                                                                       \
        int jg = (kt) * 64 + r_;                                               \
        bool v = jg < NT;                                                      \
        const __half* kg = kbase + (size_t)jg * DD + cc_;                      \
        const __half* vg = vbase + (size_t)jg * DD + cc_;                      \
        uint32_t kd = smem_u32(Ksb + (buf) * KVT + r_ * 72 + cc_);             \
        uint32_t vd = smem_u32(Vsb + (buf) * KVT + r_ * 72 + cc_);             \
        CP_A16(kd, kg, v); CP_A16(kd + 16, kg + 8, v);                         \
        CP_A16(vd, vg, v); CP_A16(vd + 16, vg + 8, v);                         \
    } while (0)

    ATT_PREF(0, 0);
    CP_COMMIT();
#pragma unroll
    for (int it = 0; it < 4; it++) {
        int idx = it * 256 + tid;
        int r = idx >> 3;
        int c8 = (idx & 7) * 8;
        int ig = qt * 128 + r;
        int4 val = make_int4(0, 0, 0, 0);
        if (ig < NT) val = *(const int4*)(qbase + (size_t)ig * DD + c8);
        *(int4*)(Qs + r * 72 + c8) = val;
    }
    __syncthreads();

    const int rowA = (lane & 7) + (((lane >> 3) & 1) << 3);
    const int colA = (lane >> 4) << 3;
    const int rowB = (lane & 7) + ((lane >> 4) << 3);
    const int colB = ((lane >> 3) & 1) << 3;

    uint32_t aq[4][4];
    {
        const int m0 = w * 16;
#pragma unroll
        for (int ks = 0; ks < 4; ks++) {
            uint32_t addr = smem_u32(Qs + (m0 + rowA) * 72 + ks * 16 + colA);
            LDSM4(aq[ks][0], aq[ks][1], aq[ks][2], aq[ks][3], addr);
        }
    }

    float o[8][4];
#pragma unroll
    for (int c = 0; c < 8; c++)
#pragma unroll
        for (int j = 0; j < 4; j++) o[c][j] = 0.0f;
    float m0r = -1e30f, m1r = -1e30f, l0 = 0.0f, l1 = 0.0f;

    for (int kt = 0; kt < NKT; kt++) {
        const int cur = kt & 1;
        if (kt < NKT - 1) {
            ATT_PREF(kt + 1, 1 - cur);
            CP_COMMIT();
            CP_WAIT1();
        } else {
            CP_WAIT0();
        }
        __syncthreads();

        const __half* Ks = Ksb + cur * KVT;
        const __half* Vs = Vsb + cur * KVT;

        float s[8][4];
#pragma unroll
        for (int c = 0; c < 8; c++)
#pragma unroll
            for (int j = 0; j < 4; j++) s[c][j] = 0.0f;

#pragma unroll
        for (int ks = 0; ks < 4; ks++) {
#pragma unroll
            for (int np = 0; np < 4; np++) {
                uint32_t b0, b1, b2, b3;
                uint32_t addr = smem_u32(Ks + (np * 16 + rowB) * 72 + ks * 16 + colB);
                LDSM4(b0, b1, b2, b3, addr);
                mma_16816(s[np * 2],     aq[ks][0], aq[ks][1], aq[ks][2], aq[ks][3], b0, b1);
                mma_16816(s[np * 2 + 1], aq[ks][0], aq[ks][1], aq[ks][2], aq[ks][3], b2, b3);
            }
        }

        // base-2 scale + tail mask (last tile: only chunk 0 = 8 keys valid)
        const bool lastk = (kt == LASTKT);
#pragma unroll
        for (int c = 0; c < 8; c++) {
#pragma unroll
            for (int j = 0; j < 4; j++) {
                float v = s[c][j] * T2;
                if (lastk && c > 0) v = -1e30f;
                s[c][j] = v;
            }
        }

        float mx0 = -1e30f, mx1 = -1e30f;
#pragma unroll
        for (int c = 0; c < 8; c++) {
            mx0 = fmaxf(mx0, fmaxf(s[c][0], s[c][1]));
            mx1 = fmaxf(mx1, fmaxf(s[c][2], s[c][3]));
        }
        mx0 = fmaxf(mx0, __shfl_xor_sync(0xffffffffu, mx0, 1));
        mx0 = fmaxf(mx0, __shfl_xor_sync(0xffffffffu, mx0, 2));
        mx1 = fmaxf(mx1, __shfl_xor_sync(0xffffffffu, mx1, 1));
        mx1 = fmaxf(mx1, __shfl_xor_sync(0xffffffffu, mx1, 2));

        float mn0 = fmaxf(m0r, mx0);
        float mn1 = fmaxf(m1r, mx1);
        float sc0 = ex2(m0r - mn0);
        float sc1 = ex2(m1r - mn1);

        float sum0 = 0.0f, sum1 = 0.0f;
        uint32_t ph0[8], ph1[8];
#pragma unroll
        for (int c = 0; c < 8; c++) {
            float p00 = ex2(s[c][0] - mn0);
            float p01 = ex2(s[c][1] - mn0);
            float p10 = ex2(s[c][2] - mn1);
            float p11 = ex2(s[c][3] - mn1);
            sum0 += p00 + p01;
            sum1 += p10 + p11;
            ph0[c] = pack_half2(p00, p01);
            ph1[c] = pack_half2(p10, p11);
        }
        sum0 += __shfl_xor_sync(0xffffffffu, sum0, 1);
        sum0 += __shfl_xor_sync(0xffffffffu, sum0, 2);
        sum1 += __shfl_xor_sync(0xffffffffu, sum1, 1);
        sum1 += __shfl_xor_sync(0xffffffffu, sum1, 2);

        l0 = l0 * sc0 + sum0;
        l1 = l1 * sc1 + sum1;
        m0r = mn0;
        m1r = mn1;
#pragma unroll
        for (int c = 0; c < 8; c++) {
            o[c][0] *= sc0; o[c][1] *= sc0;
            o[c][2] *= sc1; o[c][3] *= sc1;
        }

#pragma unroll
        for (int ks = 0; ks < 4; ks++) {
            uint32_t a0 = ph0[2 * ks], a1 = ph1[2 * ks];
            uint32_t a2 = ph0[2 * ks + 1], a3 = ph1[2 * ks + 1];
#pragma unroll
            for (int np = 0; np < 4; np++) {
                uint32_t b0, b1, b2, b3;
                uint32_t addr = smem_u32(Vs + (ks * 16 + rowA) * 72 + np * 16 + colA);
                LDSM4T(b0, b1, b2, b3, addr);
                mma_16816(o[np * 2],     a0, a1, a2, a3, b0, b1);
                mma_16816(o[np * 2 + 1], a0, a1, a2, a3, b2, b3);
            }
        }
        __syncthreads();
    }
#undef ATT_PREF

    float inv0 = 1.0f / l0;
    float inv1 = 1.0f / l1;
    int t0 = qt * 128 + w * 16 + grp;
    if (t0 < NT) {
        __half* dst = g_oh + ((size_t)bh * NT + t0) * DD;
#pragma unroll
        for (int c = 0; c < 8; c++)
            *(__half2*)(dst + c * 8 + qd * 2) =
                __floats2half2_rn(o[c][0] * inv0, o[c][1] * inv0);
    }
    int t1 = t0 + 8;
    if (t1 < NT) {
        __half* dst = g_oh + ((size_t)bh * NT + t1) * DD;
#pragma unroll
        for (int c = 0; c < 8; c++)
            *(__half2*)(dst + c * 8 + qd * 2) =
                __floats2half2_rn(o[c][2] * inv1, o[c][3] * inv1);
    }
}

// ---------------------------------------------------------------------------
// Kernel 3: output projection, fp16 MMA + cp.async. 2 CTAs/SM.
// ---------------------------------------------------------------------------
__global__ void __launch_bounds__(256, 2) out_mma_kernel(float* __restrict__ out)
{
    __shared__ __half Ah[2][128][40];
    __shared__ __half Bh[2][32][136];

    const int m0 = blockIdx.y * 128;
    const int n0 = blockIdx.x * 128;
    const int tid = threadIdx.x;
    const int w = tid >> 5;
    const int lane = tid & 31;
    const int grp = lane >> 2;
    const int qd = lane & 3;
    const int wm = w >> 1;
    const int wn = w & 1;

    const int rowA = (lane & 7) + (((lane >> 3) & 1) << 3);
    const int colA = (lane >> 4) << 3;

    const int ar = tid >> 1;
    const int ac = (tid & 1) * 16;
    const int am = m0 + ar;
    const int ab = am / NQ;
    const int at = am - ab * NQ;
    const int kr = tid >> 3;
    const int bc = (tid & 7) * 16;

#define OUT_PREF(kt, buf)                                                      \
    do {                                                                       \
        int k = (kt) * 32 + ac;                                                \
        int hh2 = k >> 6;                                                      \
        int dd2 = k & 63;                                                      \
        uint32_t ad = smem_u32(&Ah[buf][ar][ac]);                              \
        const __half* ag = g_oh + (((size_t)ab * HH + hh2) * NT + at) * DD + dd2; \
        CP_A16(ad, ag, true);                                                  \
        CP_A16(ad + 16, ag + 8, true);                                         \
        uint32_t bd = smem_u32(&Bh[buf][kr][bc]);                              \
        const __half* bg = g_wouth + (size_t)((kt) * 32 + kr) * CDIM + n0 + bc;\
        CP_A16(bd, bg, true);                                                  \
        CP_A16(bd + 16, bg + 8, true);                                         \
    } while (0)

    float acc[2][8][4];
#pragma unroll
    for (int i = 0; i < 2; i++)
#pragma unroll
        for (int j = 0; j < 8; j++)
#pragma unroll
            for (int r = 0; r < 4; r++) acc[i][j][r] = 0.0f;

    OUT_PREF(0, 0);
    CP_COMMIT();

    for (int kt = 0; kt < 16; kt++) {
        const int cur = kt & 1;
        if (kt < 15) {
            OUT_PREF(kt + 1, 1 - cur);
            CP_COMMIT();
            CP_WAIT1();
        } else {
            CP_WAIT0();
        }
        __syncthreads();
#pragma unroll
        for (int ks = 0; ks < 2; ks++) {
            uint32_t a[2][4];
#pragma unroll
            for (int mi = 0; mi < 2; mi++) {
                uint32_t addr = smem_u32(&Ah[cur][wm * 32 + mi * 16 + rowA][ks * 16 + colA]);
                LDSM4(a[mi][0], a[mi][1], a[mi][2], a[mi][3], addr);
            }
#pragma unroll
            for (int nc = 0; nc < 4; nc++) {
                uint32_t b0, b1, b2, b3;
                uint32_t addr = smem_u32(&Bh[cur][ks * 16 + rowA][wn * 64 + nc * 16 + colA]);
                LDSM4T(b0, b1, b2, b3, addr);
#pragma unroll
                for (int mi = 0; mi < 2; mi++) {
                    mma_16816(acc[mi][2 * nc],     a[mi][0], a[mi][1], a[mi][2], a[mi][3], b0, b1);
                    mma_16816(acc[mi][2 * nc + 1], a[mi][0], a[mi][1], a[mi][2], a[mi][3], b2, b3);
                }
            }
        }
        __syncthreads();
    }
#undef OUT_PREF

#pragma unroll
    for (int mi = 0; mi < 2; mi++) {
        int rbase = m0 + wm * 32 + mi * 16 + grp;
#pragma unroll
        for (int rr = 0; rr < 2; rr++) {
            int m = rbase + rr * 8;
            int b = m / NQ;
            int t = m - b * NQ;
            float* orow = out + ((size_t)b * NQ + t) * CDIM;
#pragma unroll
            for (int nc = 0; nc < 8; nc++) {
                int c = n0 + wn * 64 + nc * 8 + qd * 2;
                *(float2*)(orow + c) =
                    make_float2(acc[mi][nc][rr * 2], acc[mi][nc][rr * 2 + 1]);
            }
        }
    }
}

// ---------------------------------------------------------------------------
extern "C" void kernel_launch(void* const* d_in, const int* in_sizes, int n_in,
                              void* d_out, int out_size)
{
    const float* X    = (const float*)d_in[0];   // (4,2304,512)
    const float* S    = (const float*)d_in[1];   // (4,8,512)
    const float* Wqkv = (const float*)d_in[2];   // (512,1536)
    const float* Wout = (const float*)d_in[3];   // (512,512)
    const float* temp = (const float*)d_in[4];   // (8,1,1)
    float* out = (float*)d_out;                  // (4,2304,512)

    // 0. fp32 -> fp16 conversion
    {
        int blocks = (CVT_TOT + 255) / 256;
        convert_kernel<<<blocks, 256>>>(X, S, Wqkv, Wout);
    }
    // 1. QKV GEMM + fused l2norm epilogue
    {
        dim3 grid(1536 / 128, (M1 + 127) / 128);   // (12, 73)
        qkv_mma_kernel<<<grid, 256>>>();
    }
    // 2. Attention
    {
        size_t smem = (128 * 72 + 4 * KVT) * sizeof(__half);   // 55296 B
        (void)cudaFuncSetAttribute(attn_mma_kernel,
                                   cudaFuncAttributeMaxDynamicSharedMemorySize,
                                   (int)smem);
        dim3 grid(NQT, BB * HH);                   // (19, 32)
        attn_mma_kernel<<<grid, 256, smem>>>(temp);
    }
    // 3. Output projection
    {
        dim3 grid(CDIM / 128, M3 / 128);           // (4, 72)
        out_mma_kernel<<<grid, 256>>>(out);
    }
}

// round 9
// speedup vs baseline: 6.9454x; 1.1087x over previous
#include <cuda_runtime.h>
#include <cuda_fp16.h>
#include <cuda_bf16.h>
#include <math.h>
#include <stdint.h>

#define BB 4
#define NQ 2304
#define NT 2312           // NQ + 8 summary tokens
#define CDIM 512
#define HH 8
#define DD 64
#define M1 (BB * NT)      // 9248
#define M3 (BB * NQ)      // 9216
#define QKV_ELEMS (BB * HH * NT * DD)   // 4,734,976
#define NKT 37            // ceil(NT/64) key tiles
#define LASTKT 36
#define NQT 19            // ceil(NT/128) query tiles
#define KVT (64 * 72)     // one K or V buffer in halves

// Scratch (no allocations allowed)
__device__ __half g_xh[M1 * CDIM];        // concat(X,S) fp16
__device__ __half g_wqkvh[CDIM * 1536];   // Wqkv fp16
__device__ __half g_wouth[CDIM * CDIM];   // Wout fp16
__device__ __half g_qh[QKV_ELEMS];        // normalized q fp16
__device__ __half g_kh[QKV_ELEMS];        // normalized k fp16
__device__ __half g_vh[QKV_ELEMS];        // v fp16
__device__ __half g_oh[QKV_ELEMS];        // attention output fp16

// ---------------------------------------------------------------------------
// helpers
// ---------------------------------------------------------------------------
static __device__ __forceinline__ uint32_t smem_u32(const void* p) {
    return (uint32_t)__cvta_generic_to_shared(p);
}

#define LDSM4(r0, r1, r2, r3, addr)                                            \
    asm volatile("ldmatrix.sync.aligned.m8n8.x4.shared.b16 {%0,%1,%2,%3}, [%4];" \
                 : "=r"(r0), "=r"(r1), "=r"(r2), "=r"(r3) : "r"(addr))

#define LDSM4T(r0, r1, r2, r3, addr)                                           \
    asm volatile("ldmatrix.sync.aligned.m8n8.x4.trans.shared.b16 {%0,%1,%2,%3}, [%4];" \
                 : "=r"(r0), "=r"(r1), "=r"(r2), "=r"(r3) : "r"(addr))

static __device__ __forceinline__ void mma_16816(
    float c[4], uint32_t a0, uint32_t a1, uint32_t a2, uint32_t a3,
    uint32_t b0, uint32_t b1)
{
    asm volatile(
        "mma.sync.aligned.m16n8k16.row.col.f32.f16.f16.f32 "
        "{%0,%1,%2,%3},{%4,%5,%6,%7},{%8,%9},{%0,%1,%2,%3};"
        : "+f"(c[0]), "+f"(c[1]), "+f"(c[2]), "+f"(c[3])
        : "r"(a0), "r"(a1), "r"(a2), "r"(a3), "r"(b0), "r"(b1));
}

static __device__ __forceinline__ uint32_t pack_half2(float x, float y) {
    __half2 h = __floats2half2_rn(x, y);
    return reinterpret_cast<uint32_t&>(h);
}

static __device__ __forceinline__ float ex2(float x) {
    float r;
    asm("ex2.approx.f32 %0, %1;" : "=f"(r) : "f"(x));
    return r;
}

#define CP_A16(dst, src, valid)                                                \
    asm volatile("cp.async.ca.shared.global [%0], [%1], 16, %2;"               \
                 :: "r"(dst), "l"(src), "r"((valid) ? 16 : 0))
#define CP_COMMIT() asm volatile("cp.async.commit_group;")
#define CP_WAIT1()  asm volatile("cp.async.wait_group 1;")
#define CP_WAIT0()  asm volatile("cp.async.wait_group 0;")

// ---------------------------------------------------------------------------
// Kernel 0: fp32 -> fp16 conversion of inputs (concat X,S) and weights.
// ---------------------------------------------------------------------------
#define CVT_A   (M1 * CDIM / 4)             // 1183744
#define CVT_WQ  (CDIM * 1536 / 4)           // 196608
#define CVT_WO  (CDIM * CDIM / 4)           // 65536
#define CVT_TOT (CVT_A + CVT_WQ + CVT_WO)   // 1445888

__global__ void __launch_bounds__(256) convert_kernel(
    const float* __restrict__ X, const float* __restrict__ S,
    const float* __restrict__ Wq, const float* __restrict__ Wo)
{
    int i = blockIdx.x * 256 + threadIdx.x;
    if (i >= CVT_TOT) return;
    const float* src;
    __half* dst;
    if (i < CVT_A) {
        int row = i >> 7;
        int c4 = (i & 127) * 4;
        int b = row / NT;
        int t = row - b * NT;
        src = (t < NQ) ? X + ((size_t)b * NQ + t) * CDIM + c4
                       : S + ((size_t)b * 8 + (t - NQ)) * CDIM + c4;
        dst = g_xh + (size_t)row * CDIM + c4;
    } else if (i < CVT_A + CVT_WQ) {
        int j = (i - CVT_A) * 4;
        src = Wq + j;
        dst = g_wqkvh + j;
    } else {
        int j = (i - CVT_A - CVT_WQ) * 4;
        src = Wo + j;
        dst = g_wouth + j;
    }
    float4 v = *(const float4*)src;
    __half2 h0 = __floats2half2_rn(v.x, v.y);
    __half2 h1 = __floats2half2_rn(v.z, v.w);
    uint2 u;
    u.x = reinterpret_cast<uint32_t&>(h0);
    u.y = reinterpret_cast<uint32_t&>(h1);
    *(uint2*)dst = u;
}

// ---------------------------------------------------------------------------
// Kernel 1: QKV GEMM, fp16 MMA + cp.async double buffer.
// Epilogue: fused L2-norm for q,k -> g_qh/g_kh; v -> g_vh.
// ---------------------------------------------------------------------------
__global__ void __launch_bounds__(256, 2) qkv_mma_kernel()
{
    __shared__ __half Ah[2][128][40];
    __shared__ __half Bh[2][32][136];

    const int m0 = blockIdx.y * 128;
    const int n0 = blockIdx.x * 128;
    const int tid = threadIdx.x;
    const int w = tid >> 5;
    const int lane = tid & 31;
    const int grp = lane >> 2;
    const int qd = lane & 3;
    const int wm = w >> 1;
    const int wn = w & 1;

    const int rowA = (lane & 7) + (((lane >> 3) & 1) << 3);
    const int colA = (lane >> 4) << 3;

    const int ar = tid >> 1;
    const int ac = (tid & 1) * 16;
    const bool aok = (m0 + ar) < M1;
    const int kr = tid >> 3;
    const int bc = (tid & 7) * 16;

#define QKV_PREF(kt, buf)                                                      \
    do {                                                                       \
        uint32_t ad = smem_u32(&Ah[buf][ar][ac]);                              \
        const __half* ag = g_xh + (size_t)(m0 + ar) * CDIM + (kt) * 32 + ac;   \
        CP_A16(ad, ag, aok);                                                   \
        CP_A16(ad + 16, ag + 8, aok);                                          \
        uint32_t bd = smem_u32(&Bh[buf][kr][bc]);                              \
        const __half* bg = g_wqkvh + (size_t)((kt) * 32 + kr) * 1536 + n0 + bc;\
        CP_A16(bd, bg, true);                                                  \
        CP_A16(bd + 16, bg + 8, true);                                         \
    } while (0)

    float acc[2][8][4];
#pragma unroll
    for (int i = 0; i < 2; i++)
#pragma unroll
        for (int j = 0; j < 8; j++)
#pragma unroll
            for (int r = 0; r < 4; r++) acc[i][j][r] = 0.0f;

    QKV_PREF(0, 0);
    CP_COMMIT();

    for (int kt = 0; kt < 16; kt++) {
        const int cur = kt & 1;
        if (kt < 15) {
            QKV_PREF(kt + 1, 1 - cur);
            CP_COMMIT();
            CP_WAIT1();
        } else {
            CP_WAIT0();
        }
        __syncthreads();
#pragma unroll
        for (int ks = 0; ks < 2; ks++) {
            uint32_t a[2][4];
#pragma unroll
            for (int mi = 0; mi < 2; mi++) {
                uint32_t addr = smem_u32(&Ah[cur][wm * 32 + mi * 16 + rowA][ks * 16 + colA]);
                LDSM4(a[mi][0], a[mi][1], a[mi][2], a[mi][3], addr);
            }
#pragma unroll
            for (int nc = 0; nc < 4; nc++) {
                uint32_t b0, b1, b2, b3;
                uint32_t addr = smem_u32(&Bh[cur][ks * 16 + rowA][wn * 64 + nc * 16 + colA]);
                LDSM4T(b0, b1, b2, b3, addr);
#pragma unroll
                for (int mi = 0; mi < 2; mi++) {
                    mma_16816(acc[mi][2 * nc],     a[mi][0], a[mi][1], a[mi][2], a[mi][3], b0, b1);
                    mma_16816(acc[mi][2 * nc + 1], a[mi][0], a[mi][1], a[mi][2], a[mi][3], b2, b3);
                }
            }
        }
        __syncthreads();
    }
#undef QKV_PREF

    // Epilogue. This warp's 64 columns = one head of one of q/k/v.
    const int cbase = n0 + wn * 64;
    const int which = cbase >> 9;          // 0=q 1=k 2=v (uniform per warp)
    const int h = (cbase >> 6) & 7;
    __half* dstbase = (which == 0) ? g_qh : (which == 1) ? g_kh : g_vh;

#pragma unroll
    for (int mi = 0; mi < 2; mi++) {
#pragma unroll
        for (int rr = 0; rr < 2; rr++) {
            int m = m0 + wm * 32 + mi * 16 + rr * 8 + grp;
            float inv = 1.0f;
            if (which < 2) {
                float ss = 0.0f;
#pragma unroll
                for (int nc = 0; nc < 8; nc++) {
                    float a0 = acc[mi][nc][rr * 2];
                    float a1 = acc[mi][nc][rr * 2 + 1];
                    ss += a0 * a0 + a1 * a1;
                }
                ss += __shfl_xor_sync(0xffffffffu, ss, 1);
                ss += __shfl_xor_sync(0xffffffffu, ss, 2);
                inv = 1.0f / fmaxf(sqrtf(ss), 1e-12f);
            }
            if (m < M1) {
                int b = m / NT;
                int t = m - b * NT;
                __half* dst = dstbase + (((size_t)b * HH + h) * NT + t) * DD;
#pragma unroll
                for (int nc = 0; nc < 8; nc++) {
                    *(__half2*)(dst + nc * 8 + qd * 2) = __floats2half2_rn(
                        acc[mi][nc][rr * 2] * inv, acc[mi][nc][rr * 2 + 1] * inv);
                }
            }
        }
    }
}

// ---------------------------------------------------------------------------
// Kernel 2: Flash attention, fp16 MMA + cp.async double-buffered K/V.
// FIXED-MAX softmax: q,k unit vectors => |score| <= 1 => scaled score
// bounded by M = |T2|. No running max, no rescale, no in-loop reductions.
// ---------------------------------------------------------------------------
__global__ void __launch_bounds__(256, 2) attn_mma_kernel(const float* __restrict__ temp)
{
    extern __shared__ __half dynsm[];
    __half* Qs  = dynsm;                   // 128*72
    __half* Ksb = dynsm + 128 * 72;        // 2 * KVT
    __half* Vsb = Ksb + 2 * KVT;           // 2 * KVT

    const int bh = blockIdx.y;
    const int h = bh & (HH - 1);
    const int qt = blockIdx.x;
    const int tid = threadIdx.x;
    const int w = tid >> 5;
    const int lane = tid & 31;
    const int grp = lane >> 2;
    const int qd = lane & 3;
    const float T2 = temp[h] * 1.44269504089f;   // base-2 scale
    const float negM = -fabsf(T2) - 0.01f;       // fixed softmax "max" bound

    const __half* qbase = g_qh + (size_t)bh * NT * DD;
    const __half* kbase = g_kh + (size_t)bh * NT * DD;
    const __half* vbase = g_vh + (size_t)bh * NT * DD;

    const int r_ = tid >> 2;           // 0..63
    const int cc_ = (tid & 3) * 16;    // 0,16,32,48

#define ATT_PREF(kt, buf)                                                      \
    do {                                                                       \
        int jg = (kt) * 64 + r_;                                               \
        bool v = jg < NT;                                                      \
        const __half* kg = kbase + (size_t)jg * DD + cc_;                      \
        const __half* vg = vbase + (size_t)jg * DD + cc_;                      \
        uint32_t kd = smem_u32(Ksb + (buf) * KVT + r_ * 72 + cc_);             \
        uint32_t vd = smem_u32(Vsb + (buf) * KVT + r_ * 72 + cc_);             \
        CP_A16(kd, kg, v); CP_A16(kd + 16, kg + 8, v);                         \
        CP_A16(vd, vg, v); CP_A16(vd + 16, vg + 8, v);                         \
    } while (0)

    ATT_PREF(0, 0);
    CP_COMMIT();
#pragma unroll
    for (int it = 0; it < 4; it++) {
        int idx = it * 256 + tid;
        int r = idx >> 3;
        int c8 = (idx & 7) * 8;
        int ig = qt * 128 + r;
        int4 val = make_int4(0, 0, 0, 0);
        if (ig < NT) val = *(const int4*)(qbase + (size_t)ig * DD + c8);
        *(int4*)(Qs + r * 72 + c8) = val;
    }
    __syncthreads();

    const int rowA = (lane & 7) + (((lane >> 3) & 1) << 3);
    const int colA = (lane >> 4) << 3;
    const int rowB = (lane & 7) + ((lane >> 4) << 3);
    const int colB = ((lane >> 3) & 1) << 3;

    uint32_t aq[4][4];
    {
        const int m0 = w * 16;
#pragma unroll
        for (int ks = 0; ks < 4; ks++) {
            uint32_t addr = smem_u32(Qs + (m0 + rowA) * 72 + ks * 16 + colA);
            LDSM4(aq[ks][0], aq[ks][1], aq[ks][2], aq[ks][3], addr);
        }
    }

    float o[8][4];
#pragma unroll
    for (int c = 0; c < 8; c++)
#pragma unroll
        for (int j = 0; j < 4; j++) o[c][j] = 0.0f;
    float l0 = 0.0f, l1 = 0.0f;           // raw sums, reduced in epilogue

    for (int kt = 0; kt < NKT; kt++) {
        const int cur = kt & 1;
        if (kt < NKT - 1) {
            ATT_PREF(kt + 1, 1 - cur);
            CP_COMMIT();
            CP_WAIT1();
        } else {
            CP_WAIT0();
        }
        __syncthreads();

        const __half* Ks = Ksb + cur * KVT;
        const __half* Vs = Vsb + cur * KVT;

        float s[8][4];
#pragma unroll
        for (int c = 0; c < 8; c++)
#pragma unroll
            for (int j = 0; j < 4; j++) s[c][j] = 0.0f;

#pragma unroll
        for (int ks = 0; ks < 4; ks++) {
#pragma unroll
            for (int np = 0; np < 4; np++) {
                uint32_t b0, b1, b2, b3;
                uint32_t addr = smem_u32(Ks + (np * 16 + rowB) * 72 + ks * 16 + colB);
                LDSM4(b0, b1, b2, b3, addr);
                mma_16816(s[np * 2],     aq[ks][0], aq[ks][1], aq[ks][2], aq[ks][3], b0, b1);
                mma_16816(s[np * 2 + 1], aq[ks][0], aq[ks][1], aq[ks][2], aq[ks][3], b2, b3);
            }
        }

        // p = 2^(s*T2 - M); tail tile: only chunk 0 (8 keys) valid
        const bool lastk = (kt == LASTKT);
        uint32_t ph0[8], ph1[8];
#pragma unroll
        for (int c = 0; c < 8; c++) {
            float p00 = ex2(fmaf(s[c][0], T2, negM));
            float p01 = ex2(fmaf(s[c][1], T2, negM));
            float p10 = ex2(fmaf(s[c][2], T2, negM));
            float p11 = ex2(fmaf(s[c][3], T2, negM));
            if (lastk && c > 0) { p00 = p01 = p10 = p11 = 0.0f; }
            l0 += p00 + p01;
            l1 += p10 + p11;
            ph0[c] = pack_half2(p00, p01);
            ph1[c] = pack_half2(p10, p11);
        }

#pragma unroll
        for (int ks = 0; ks < 4; ks++) {
            uint32_t a0 = ph0[2 * ks], a1 = ph1[2 * ks];
            uint32_t a2 = ph0[2 * ks + 1], a3 = ph1[2 * ks + 1];
#pragma unroll
            for (int np = 0; np < 4; np++) {
                uint32_t b0, b1, b2, b3;
                uint32_t addr = smem_u32(Vs + (ks * 16 + rowA) * 72 + np * 16 + colA);
                LDSM4T(b0, b1, b2, b3, addr);
                mma_16816(o[np * 2],     a0, a1, a2, a3, b0, b1);
                mma_16816(o[np * 2 + 1], a0, a1, a2, a3, b2, b3);
            }
        }
        __syncthreads();
    }
#undef ATT_PREF

    // Epilogue: reduce row sums across the quad, normalize, write g_oh
    l0 += __shfl_xor_sync(0xffffffffu, l0, 1);
    l0 += __shfl_xor_sync(0xffffffffu, l0, 2);
    l1 += __shfl_xor_sync(0xffffffffu, l1, 1);
    l1 += __shfl_xor_sync(0xffffffffu, l1, 2);
    float inv0 = 1.0f / l0;
    float inv1 = 1.0f / l1;
    int t0 = qt * 128 + w * 16 + grp;
    if (t0 < NT) {
        __half* dst = g_oh + ((size_t)bh * NT + t0) * DD;
#pragma unroll
        for (int c = 0; c < 8; c++)
            *(__half2*)(dst + c * 8 + qd * 2) =
                __floats2half2_rn(o[c][0] * inv0, o[c][1] * inv0);
    }
    int t1 = t0 + 8;
    if (t1 < NT) {
        __half* dst = g_oh + ((size_t)bh * NT + t1) * DD;
#pragma unroll
        for (int c = 0; c < 8; c++)
            *(__half2*)(dst + c * 8 + qd * 2) =
                __floats2half2_rn(o[c][2] * inv1, o[c][3] * inv1);
    }
}

// ---------------------------------------------------------------------------
// Kernel 3: output projection, fp16 MMA + cp.async.
// ---------------------------------------------------------------------------
__global__ void __launch_bounds__(256, 2) out_mma_kernel(float* __restrict__ out)
{
    __shared__ __half Ah[2][128][40];
    __shared__ __half Bh[2][32][136];

    const int m0 = blockIdx.y * 128;
    const int n0 = blockIdx.x * 128;
    const int tid = threadIdx.x;
    const int w = tid >> 5;
    const int lane = tid & 31;
    const int grp = lane >> 2;
    const int qd = lane & 3;
    const int wm = w >> 1;
    const int wn = w & 1;

    const int rowA = (lane & 7) + (((lane >> 3) & 1) << 3);
    const int colA = (lane >> 4) << 3;

    const int ar = tid >> 1;
    const int ac = (tid & 1) * 16;
    const int am = m0 + ar;
    const int ab = am / NQ;
    const int at = am - ab * NQ;
    const int kr = tid >> 3;
    const int bc = (tid & 7) * 16;

#define OUT_PREF(kt, buf)                                                      \
    do {                                                                       \
        int k = (kt) * 32 + ac;                                                \
        int hh2 = k >> 6;                                                      \
        int dd2 = k & 63;                                                      \
        uint32_t ad = smem_u32(&Ah[buf][ar][ac]);                              \
        const __half* ag = g_oh + (((size_t)ab * HH + hh2) * NT + at) * DD + dd2; \
        CP_A16(ad, ag, true);                                                  \
        CP_A16(ad + 16, ag + 8, true);                                         \
        uint32_t bd = smem_u32(&Bh[buf][kr][bc]);                              \
        const __half* bg = g_wouth + (size_t)((kt) * 32 + kr) * CDIM + n0 + bc;\
        CP_A16(bd, bg, true);                                                  \
        CP_A16(bd + 16, bg + 8, true);                                         \
    } while (0)

    float acc[2][8][4];
#pragma unroll
    for (int i = 0; i < 2; i++)
#pragma unroll
        for (int j = 0; j < 8; j++)
#pragma unroll
            for (int r = 0; r < 4; r++) acc[i][j][r] = 0.0f;

    OUT_PREF(0, 0);
    CP_COMMIT();

    for (int kt = 0; kt < 16; kt++) {
        const int cur = kt & 1;
        if (kt < 15) {
            OUT_PREF(kt + 1, 1 - cur);
            CP_COMMIT();
            CP_WAIT1();
        } else {
            CP_WAIT0();
        }
        __syncthreads();
#pragma unroll
        for (int ks = 0; ks < 2; ks++) {
            uint32_t a[2][4];
#pragma unroll
            for (int mi = 0; mi < 2; mi++) {
                uint32_t addr = smem_u32(&Ah[cur][wm * 32 + mi * 16 + rowA][ks * 16 + colA]);
                LDSM4(a[mi][0], a[mi][1], a[mi][2], a[mi][3], addr);
            }
#pragma unroll
            for (int nc = 0; nc < 4; nc++) {
                uint32_t b0, b1, b2, b3;
                uint32_t addr = smem_u32(&Bh[cur][ks * 16 + rowA][wn * 64 + nc * 16 + colA]);
                LDSM4T(b0, b1, b2, b3, addr);
#pragma unroll
                for (int mi = 0; mi < 2; mi++) {
                    mma_16816(acc[mi][2 * nc],     a[mi][0], a[mi][1], a[mi][2], a[mi][3], b0, b1);
                    mma_16816(acc[mi][2 * nc + 1], a[mi][0], a[mi][1], a[mi][2], a[mi][3], b2, b3);
                }
            }
        }
        __syncthreads();
    }
#undef OUT_PREF

#pragma unroll
    for (int mi = 0; mi < 2; mi++) {
        int rbase = m0 + wm * 32 + mi * 16 + grp;
#pragma unroll
        for (int rr = 0; rr < 2; rr++) {
            int m = rbase + rr * 8;
            int b = m / NQ;
            int t = m - b * NQ;
            float* orow = out + ((size_t)b * NQ + t) * CDIM;
#pragma unroll
            for (int nc = 0; nc < 8; nc++) {
                int c = n0 + wn * 64 + nc * 8 + qd * 2;
                *(float2*)(orow + c) =
                    make_float2(acc[mi][nc][rr * 2], acc[mi][nc][rr * 2 + 1]);
            }
        }
    }
}

// ---------------------------------------------------------------------------
extern "C" void kernel_launch(void* const* d_in, const int* in_sizes, int n_in,
                              void* d_out, int out_size)
{
    const float* X    = (const float*)d_in[0];   // (4,2304,512)
    const float* S    = (const float*)d_in[1];   // (4,8,512)
    const float* Wqkv = (const float*)d_in[2];   // (512,1536)
    const float* Wout = (const float*)d_in[3];   // (512,512)
    const float* temp = (const float*)d_in[4];   // (8,1,1)
    float* out = (float*)d_out;                  // (4,2304,512)

    // 0. fp32 -> fp16 conversion
    {
        int blocks = (CVT_TOT + 255) / 256;
        convert_kernel<<<blocks, 256>>>(X, S, Wqkv, Wout);
    }
    // 1. QKV GEMM + fused l2norm epilogue
    {
        dim3 grid(1536 / 128, (M1 + 127) / 128);   // (12, 73)
        qkv_mma_kernel<<<grid, 256>>>();
    }
    // 2. Attention (fixed-max softmax)
    {
        size_t smem = (128 * 72 + 4 * KVT) * sizeof(__half);   // 55296 B
        (void)cudaFuncSetAttribute(attn_mma_kernel,
                                   cudaFuncAttributeMaxDynamicSharedMemorySize,
                                   (int)smem);
        dim3 grid(NQT, BB * HH);                   // (19, 32)
        attn_mma_kernel<<<grid, 256, smem>>>(temp);
    }
    // 3. Output projection
    {
        dim3 grid(CDIM / 128, M3 / 128);           // (4, 72)
        out_mma_kernel<<<grid, 256>>>(out);
    }
}